// round 10
// baseline (speedup 1.0000x reference)
#include <cuda_runtime.h>
#include <cuda_bf16.h>
#include <math.h>
#include <stdint.h>

#define N_TOK 4096
#define D_IN  512
#define E_EXP 8
#define TOPK  2
#define H_DIM 2048

#define BM 128
#define BN 128
#define BK 32
#define SLOTS (N_TOK*TOPK + E_EXP*BM)   // 9216 padded slots

// smem: 4 planes (Ah, Al, Bh, Bl), each 128 rows x 32 bf16 (64B/row), XOR-swizzled
#define PLANE_BYTES 8192
#define OAH 0
#define OAL 8192
#define OBH 16384
#define OBL 24576
#define STAGE_BYTES 32768
#define NSTAGE 3
#define SMEM_BYTES (NSTAGE * STAGE_BYTES)   // 98304

// -------- scratch (device globals; no allocation allowed) --------
__device__ int   g_counts[E_EXP];
__device__ int   g_cnt2[E_EXP];
__device__ int   g_off[E_EXP + 1];
__device__ int   g_slot_tok[SLOTS];
__device__ float g_slot_w[SLOTS];
__device__ int   g_tok_slot[N_TOK * TOPK];
__device__ float g_topw[N_TOK * TOPK];
__device__ int   g_topi[N_TOK * TOPK];

__device__ __nv_bfloat16 gx_hi[(size_t)N_TOK * D_IN];
__device__ __nv_bfloat16 gx_lo[(size_t)N_TOK * D_IN];
__device__ __nv_bfloat16 gW1t_hi[(size_t)E_EXP * H_DIM * D_IN]; // [e][n][k]
__device__ __nv_bfloat16 gW1t_lo[(size_t)E_EXP * H_DIM * D_IN];
__device__ __nv_bfloat16 gW2t_hi[(size_t)E_EXP * D_IN * H_DIM]; // [e][n][k]
__device__ __nv_bfloat16 gW2t_lo[(size_t)E_EXP * D_IN * H_DIM];
__device__ __nv_bfloat16 gh_hi[(size_t)SLOTS * H_DIM];
__device__ __nv_bfloat16 gh_lo[(size_t)SLOTS * H_DIM];
__device__ float g_ybuf[(size_t)SLOTS * D_IN];

// -------- helpers --------
__device__ __forceinline__ void cp16(uint32_t dst, const void* src, int srcBytes) {
    asm volatile("cp.async.cg.shared.global [%0], [%1], 16, %2;"
                 :: "r"(dst), "l"(src), "r"(srcBytes) : "memory");
}
__device__ __forceinline__ void cp_commit() {
    asm volatile("cp.async.commit_group;" ::: "memory");
}
template<int N> __device__ __forceinline__ void cp_wait() {
    asm volatile("cp.async.wait_group %0;" :: "n"(N) : "memory");
}
__device__ __forceinline__ void ldsm4(uint32_t* r, uint32_t addr) {
    asm volatile("ldmatrix.sync.aligned.m8n8.x4.shared.b16 {%0,%1,%2,%3}, [%4];"
                 : "=r"(r[0]), "=r"(r[1]), "=r"(r[2]), "=r"(r[3]) : "r"(addr));
}
__device__ __forceinline__ void mma_bf16(float d[4],
                                         uint32_t a0, uint32_t a1, uint32_t a2, uint32_t a3,
                                         uint32_t b0, uint32_t b1) {
    asm volatile(
        "mma.sync.aligned.m16n8k16.row.col.f32.bf16.bf16.f32 "
        "{%0,%1,%2,%3},{%4,%5,%6,%7},{%8,%9},{%0,%1,%2,%3};"
        : "+f"(d[0]), "+f"(d[1]), "+f"(d[2]), "+f"(d[3])
        : "r"(a0), "r"(a1), "r"(a2), "r"(a3), "r"(b0), "r"(b1));
}
// swizzled byte offset of 16B chunk c (0..3) in row r of a plane
__device__ __forceinline__ uint32_t swz(int r, int c) {
    return (uint32_t)(r * 64 + ((c ^ ((r >> 1) & 3)) * 16));
}
__device__ __forceinline__ uint32_t pack2(float a, float b) {
    __nv_bfloat162 h;
    h.x = __float2bfloat16(a);
    h.y = __float2bfloat16(b);
    return *(uint32_t*)&h;
}

// -------- 1: fused W1+W2 transpose/split + routing-state init --------
__global__ void split_wt_all_kernel(const float* __restrict__ W1,
                                    const float* __restrict__ W2) {
    if (blockIdx.z == 0 && blockIdx.y == 0) {
        int idx = blockIdx.x * blockDim.x + threadIdx.x;
        if (idx < SLOTS) g_slot_tok[idx] = -1;
        if (idx < E_EXP) { g_counts[idx] = 0; g_cnt2[idx] = 0; }
    }
    int z = blockIdx.z;
    const float* src; __nv_bfloat16 *dhi, *dlo; int K, N, e;
    if (z < E_EXP) { e = z;         src = W1; dhi = gW1t_hi; dlo = gW1t_lo; K = D_IN;  N = H_DIM; }
    else           { e = z - E_EXP; src = W2; dhi = gW2t_hi; dlo = gW2t_lo; K = H_DIM; N = D_IN;  }
    int n0 = blockIdx.x * 32, k0 = blockIdx.y * 32;
    if (n0 >= N || k0 >= K) return;

    __shared__ float t[32][33];
    const float* s = src + (size_t)e * K * N;
    int tx = threadIdx.x & 31, ty = threadIdx.x >> 5;
#pragma unroll
    for (int i = 0; i < 4; i++)
        t[ty + 8 * i][tx] = s[(size_t)(k0 + ty + 8 * i) * N + n0 + tx];
    __syncthreads();
    size_t ob = (size_t)e * K * N;
#pragma unroll
    for (int i = 0; i < 4; i++) {
        int n = n0 + ty + 8 * i, k = k0 + tx;
        float v = t[tx][ty + 8 * i];
        __nv_bfloat16 h = __float2bfloat16(v);
        dhi[ob + (size_t)n * K + k] = h;
        dlo[ob + (size_t)n * K + k] = __float2bfloat16(v - __bfloat162float(h));
    }
}

// -------- 2: gating + x hi/lo split (one warp per token) --------
__global__ void gate_kernel(const float* __restrict__ x,
                            const float* __restrict__ Wg,
                            const float* __restrict__ bg,
                            float* __restrict__ gates_out) {
    int t    = (blockIdx.x * blockDim.x + threadIdx.x) >> 5;
    int lane = threadIdx.x & 31;
    if (t >= N_TOK) return;
    const float* xr = x + (size_t)t * D_IN;

    float acc[E_EXP];
#pragma unroll
    for (int e = 0; e < E_EXP; e++) acc[e] = 0.f;
#pragma unroll
    for (int i = 0; i < 4; i++) {
        int d0 = i * 128 + lane * 4;
        float4 xv = *(const float4*)(xr + d0);
        uint32_t h0 = pack2(xv.x, xv.y), h1 = pack2(xv.z, xv.w);
        __nv_bfloat162* hp = (__nv_bfloat162*)&h0;
        __nv_bfloat162* hp1 = (__nv_bfloat162*)&h1;
        uint32_t l0 = pack2(xv.x - __bfloat162float(hp->x),  xv.y - __bfloat162float(hp->y));
        uint32_t l1 = pack2(xv.z - __bfloat162float(hp1->x), xv.w - __bfloat162float(hp1->y));
        size_t o = (size_t)t * D_IN + d0;
        *(uint2*)(gx_hi + o) = make_uint2(h0, h1);
        *(uint2*)(gx_lo + o) = make_uint2(l0, l1);
        float xs[4] = {xv.x, xv.y, xv.z, xv.w};
#pragma unroll
        for (int j = 0; j < 4; j++) {
            const float4* wr = (const float4*)(Wg + (d0 + j) * E_EXP);
            float4 w0 = wr[0], w1 = wr[1];
            acc[0] = fmaf(xs[j], w0.x, acc[0]); acc[1] = fmaf(xs[j], w0.y, acc[1]);
            acc[2] = fmaf(xs[j], w0.z, acc[2]); acc[3] = fmaf(xs[j], w0.w, acc[3]);
            acc[4] = fmaf(xs[j], w1.x, acc[4]); acc[5] = fmaf(xs[j], w1.y, acc[5]);
            acc[6] = fmaf(xs[j], w1.z, acc[6]); acc[7] = fmaf(xs[j], w1.w, acc[7]);
        }
    }
#pragma unroll
    for (int o = 16; o > 0; o >>= 1) {
#pragma unroll
        for (int e = 0; e < E_EXP; e++)
            acc[e] += __shfl_xor_sync(0xffffffffu, acc[e], o);
    }
    if (lane == 0) {
        float l[E_EXP], p[E_EXP];
        float m = -1e30f;
#pragma unroll
        for (int e = 0; e < E_EXP; e++) { l[e] = acc[e] + bg[e]; m = fmaxf(m, l[e]); }
        float s = 0.f;
#pragma unroll
        for (int e = 0; e < E_EXP; e++) { p[e] = __expf(l[e] - m); s += p[e]; }
        float inv = 1.f / s;
#pragma unroll
        for (int e = 0; e < E_EXP; e++) p[e] *= inv;
        if (gates_out) {
#pragma unroll
            for (int e = 0; e < E_EXP; e++) gates_out[t * E_EXP + e] = p[e];
        }
        int i1 = 0; float p1 = p[0];
#pragma unroll
        for (int e = 1; e < E_EXP; e++) if (p[e] > p1) { p1 = p[e]; i1 = e; }
        int i2 = -1; float p2 = -1.f;
#pragma unroll
        for (int e = 0; e < E_EXP; e++) if (e != i1 && p[e] > p2) { p2 = p[e]; i2 = e; }
        g_topw[t * 2 + 0] = p1;  g_topi[t * 2 + 0] = i1;
        g_topw[t * 2 + 1] = p2;  g_topi[t * 2 + 1] = i2;
        atomicAdd(&g_counts[i1], 1);
        atomicAdd(&g_counts[i2], 1);
    }
}

// -------- 3: scatter (scan folded in) --------
__global__ void scatter_kernel() {
    __shared__ int soff[E_EXP + 1];
    if (threadIdx.x == 0) {
        int o = 0;
#pragma unroll
        for (int e = 0; e < E_EXP; e++) {
            soff[e] = o;
            o += ((g_counts[e] + BM - 1) / BM) * BM;
        }
        soff[E_EXP] = o;
        if (blockIdx.x == 0) {
#pragma unroll
            for (int e = 0; e <= E_EXP; e++) g_off[e] = soff[e];
        }
    }
    __syncthreads();
    int i = blockIdx.x * blockDim.x + threadIdx.x;
    if (i >= N_TOK * TOPK) return;
    int e = g_topi[i];
    int pos = soff[e] + atomicAdd(&g_cnt2[e], 1);
    g_slot_tok[pos] = i >> 1;
    g_slot_w[pos]   = g_topw[i];
    g_tok_slot[i]   = pos;
}

// -------- grouped bf16x3 GEMM, pass-major MMA scheduling --------
template<int KTOT, int NTOT, bool GATHER, bool RELU, bool SCALE>
__global__ void __launch_bounds__(256, 2)
mma_gemm_kernel(const __nv_bfloat16* __restrict__ Ahi,
                const __nv_bfloat16* __restrict__ Alo,
                const __nv_bfloat16* __restrict__ Bthi,
                const __nv_bfloat16* __restrict__ Btlo,
                const float* __restrict__ Bias)
{
    constexpr int KT = KTOT / BK;
    extern __shared__ char smem[];
    __shared__ int   sTok[BM];
    __shared__ float sW[BM];

    const int m0 = blockIdx.y * BM;
    const int n0 = blockIdx.x * BN;
    if (m0 >= g_off[E_EXP]) return;
    int e = 0;
#pragma unroll
    for (int i = 1; i < E_EXP; i++) if (m0 >= g_off[i]) e = i;

    const int tid = threadIdx.x;
    if (tid < BM) {
        if (GATHER) sTok[tid] = g_slot_tok[m0 + tid];
        if (SCALE)  sW[tid]   = g_slot_w[m0 + tid];
    }
    __syncthreads();

    const __nv_bfloat16* Wh = Bthi + (size_t)e * NTOT * KTOT;
    const __nv_bfloat16* Wl = Btlo + (size_t)e * NTOT * KTOT;

    const int srow = tid >> 1;
    const int skoff = (tid & 1) * 16;

    const __nv_bfloat16 *arow_h, *arow_l;
    int abytes = 16;
    if (GATHER) {
        int tok = sTok[srow];
        if (tok >= 0) {
            arow_h = Ahi + (size_t)tok * KTOT + skoff;
            arow_l = Alo + (size_t)tok * KTOT + skoff;
        } else { arow_h = Ahi; arow_l = Alo; abytes = 0; }
    } else {
        arow_h = Ahi + (size_t)(m0 + srow) * KTOT + skoff;
        arow_l = Alo + (size_t)(m0 + srow) * KTOT + skoff;
    }
    const __nv_bfloat16* brow_h = Wh + (size_t)(n0 + srow) * KTOT + skoff;
    const __nv_bfloat16* brow_l = Wl + (size_t)(n0 + srow) * KTOT + skoff;

    const uint32_t sbase = (uint32_t)__cvta_generic_to_shared(smem);
    const uint32_t d0 = swz(srow, 2 * (tid & 1));
    const uint32_t d1 = swz(srow, 2 * (tid & 1) + 1);

    auto stage = [&](int buf, int k0) {
        uint32_t sb = sbase + buf * STAGE_BYTES;
        cp16(sb + OAH + d0, arow_h + k0,     abytes);
        cp16(sb + OAH + d1, arow_h + k0 + 8, abytes);
        cp16(sb + OAL + d0, arow_l + k0,     abytes);
        cp16(sb + OAL + d1, arow_l + k0 + 8, abytes);
        cp16(sb + OBH + d0, brow_h + k0,     16);
        cp16(sb + OBH + d1, brow_h + k0 + 8, 16);
        cp16(sb + OBL + d0, brow_l + k0,     16);
        cp16(sb + OBL + d1, brow_l + k0 + 8, 16);
        cp_commit();
    };

    const int lane = tid & 31;
    const int wm = (tid >> 5) >> 2;  // 0..1
    const int wn = (tid >> 5) & 3;   // 0..3
    const int g  = lane >> 3;
    const int lr = lane & 7;

    const int arow0 = wm * 64 + lr + (g & 1) * 8;
    const uint32_t aswz = ((uint32_t)(arow0 >> 1) & 3);
    uint32_t aoff[2];
#pragma unroll
    for (int ks = 0; ks < 2; ks++)
        aoff[ks] = (uint32_t)(arow0 * 64) + (((uint32_t)(ks * 2 + (g >> 1)) ^ aswz) * 16);

    const int brow0 = wn * 32 + lr + ((g >> 1) & 1) * 8;
    const uint32_t bswz = ((uint32_t)(brow0 >> 1) & 3);
    uint32_t boff[2];
#pragma unroll
    for (int ks = 0; ks < 2; ks++)
        boff[ks] = (uint32_t)(brow0 * 64) + (((uint32_t)(ks * 2 + (g & 1)) ^ bswz) * 16);

    float acc[4][4][4];
#pragma unroll
    for (int mt = 0; mt < 4; mt++)
#pragma unroll
        for (int nt = 0; nt < 4; nt++)
#pragma unroll
            for (int i = 0; i < 4; i++) acc[mt][nt][i] = 0.f;

    stage(0, 0);
    stage(1, BK);
    int buf = 0;
    for (int kt = 0; kt < KT; kt++) {
        if (kt < KT - 1) cp_wait<1>(); else cp_wait<0>();
        __syncthreads();
        if (kt + 2 < KT) {
            int nb = buf + 2; if (nb >= NSTAGE) nb -= NSTAGE;
            stage(nb, (kt + 2) * BK);
        }
        const uint32_t sb = sbase + buf * STAGE_BYTES;
#pragma unroll
        for (int ks = 0; ks < 2; ks++) {
            // load B-hi + A-hi fragments
            uint32_t bh[8];
#pragma unroll
            for (int np = 0; np < 2; np++)
                ldsm4(&bh[np * 4], sb + OBH + boff[ks] + np * 1024);
            uint32_t ah[4][4];
#pragma unroll
            for (int mt = 0; mt < 4; mt++)
                ldsm4(ah[mt], sb + OAH + aoff[ks] + mt * 1024);
            // pass 1: ah x bh  (16 independent MMAs)
#pragma unroll
            for (int mt = 0; mt < 4; mt++)
#pragma unroll
                for (int nt = 0; nt < 4; nt++) {
                    int i0 = (nt >> 1) * 4 + (nt & 1) * 2;
                    mma_bf16(acc[mt][nt], ah[mt][0], ah[mt][1], ah[mt][2], ah[mt][3],
                             bh[i0], bh[i0 + 1]);
                }
            // load A-lo fragments
            uint32_t al[4][4];
#pragma unroll
            for (int mt = 0; mt < 4; mt++)
                ldsm4(al[mt], sb + OAL + aoff[ks] + mt * 1024);
            // pass 2: al x bh
#pragma unroll
            for (int mt = 0; mt < 4; mt++)
#pragma unroll
                for (int nt = 0; nt < 4; nt++) {
                    int i0 = (nt >> 1) * 4 + (nt & 1) * 2;
                    mma_bf16(acc[mt][nt], al[mt][0], al[mt][1], al[mt][2], al[mt][3],
                             bh[i0], bh[i0 + 1]);
                }
            // load B-lo fragments
            uint32_t bl[8];
#pragma unroll
            for (int np = 0; np < 2; np++)
                ldsm4(&bl[np * 4], sb + OBL + boff[ks] + np * 1024);
            // pass 3: ah x bl
#pragma unroll
            for (int mt = 0; mt < 4; mt++)
#pragma unroll
                for (int nt = 0; nt < 4; nt++) {
                    int i0 = (nt >> 1) * 4 + (nt & 1) * 2;
                    mma_bf16(acc[mt][nt], ah[mt][0], ah[mt][1], ah[mt][2], ah[mt][3],
                             bl[i0], bl[i0 + 1]);
                }
        }
        buf++; if (buf >= NSTAGE) buf = 0;
    }

    const int r = lane >> 2;
    const int c = lane & 3;
    const float* bias = Bias + (size_t)e * NTOT;
#pragma unroll
    for (int mt = 0; mt < 4; mt++) {
        int row0 = m0 + wm * 64 + mt * 16 + r;
        int lrow = wm * 64 + mt * 16 + r;
#pragma unroll
        for (int nt = 0; nt < 4; nt++) {
            int col = n0 + wn * 32 + nt * 8 + 2 * c;
            float b0v = bias[col], b1v = bias[col + 1];
            float v0 = acc[mt][nt][0] + b0v, v1 = acc[mt][nt][1] + b1v;
            float v2 = acc[mt][nt][2] + b0v, v3 = acc[mt][nt][3] + b1v;
            if (RELU) {
                v0 = fmaxf(v0, 0.f); v1 = fmaxf(v1, 0.f);
                v2 = fmaxf(v2, 0.f); v3 = fmaxf(v3, 0.f);
                size_t o0 = (size_t)row0 * NTOT + col;
                size_t o2 = o0 + (size_t)8 * NTOT;
                __nv_bfloat16 h;
                h = __float2bfloat16(v0); gh_hi[o0]     = h; gh_lo[o0]     = __float2bfloat16(v0 - __bfloat162float(h));
                h = __float2bfloat16(v1); gh_hi[o0 + 1] = h; gh_lo[o0 + 1] = __float2bfloat16(v1 - __bfloat162float(h));
                h = __float2bfloat16(v2); gh_hi[o2]     = h; gh_lo[o2]     = __float2bfloat16(v2 - __bfloat162float(h));
                h = __float2bfloat16(v3); gh_hi[o2 + 1] = h; gh_lo[o2 + 1] = __float2bfloat16(v3 - __bfloat162float(h));
            } else {
                float w0 = SCALE ? sW[lrow]     : 1.f;
                float w1 = SCALE ? sW[lrow + 8] : 1.f;
                float* o0 = g_ybuf + (size_t)row0 * NTOT + col;
                *(float2*)o0 = make_float2(v0 * w0, v1 * w0);
                *(float2*)(o0 + (size_t)8 * NTOT) = make_float2(v2 * w1, v3 * w1);
            }
        }
    }
}

// -------- 6: deterministic combine --------
__global__ void combine_kernel(float* __restrict__ out) {
    int i = blockIdx.x * blockDim.x + threadIdx.x;
    if (i >= N_TOK * (D_IN / 4)) return;
    int t  = i >> 7;
    int dd = (i & 127) << 2;
    int s0 = g_tok_slot[t * 2 + 0];
    int s1 = g_tok_slot[t * 2 + 1];
    float4 a = *(const float4*)(g_ybuf + (size_t)s0 * D_IN + dd);
    float4 b = *(const float4*)(g_ybuf + (size_t)s1 * D_IN + dd);
    float4 r = make_float4(a.x + b.x, a.y + b.y, a.z + b.z, a.w + b.w);
    *(float4*)(out + (size_t)t * D_IN + dd) = r;
}

extern "C" void kernel_launch(void* const* d_in, const int* in_sizes, int n_in,
                              void* d_out, int out_size) {
    const float* x  = (const float*)d_in[0];
    const float* Wg = (const float*)d_in[1];
    const float* bg = (const float*)d_in[2];
    const float* W1 = (const float*)d_in[3];
    const float* b1 = (const float*)d_in[4];
    const float* W2 = (const float*)d_in[5];
    const float* b2 = (const float*)d_in[6];
    float* out = (float*)d_out;

    float* gates_out = nullptr;
    if (out_size >= N_TOK * D_IN + N_TOK * E_EXP)
        gates_out = out + (size_t)N_TOK * D_IN;

    cudaFuncSetAttribute(mma_gemm_kernel<D_IN, H_DIM, true, true, false>,
                         cudaFuncAttributeMaxDynamicSharedMemorySize, SMEM_BYTES);
    cudaFuncSetAttribute(mma_gemm_kernel<H_DIM, D_IN, false, false, true>,
                         cudaFuncAttributeMaxDynamicSharedMemorySize, SMEM_BYTES);

    __nv_bfloat16 *xhi, *xlo, *w1h, *w1l, *w2h, *w2l, *hhi, *hlo;
    cudaGetSymbolAddress((void**)&xhi, gx_hi);
    cudaGetSymbolAddress((void**)&xlo, gx_lo);
    cudaGetSymbolAddress((void**)&w1h, gW1t_hi);
    cudaGetSymbolAddress((void**)&w1l, gW1t_lo);
    cudaGetSymbolAddress((void**)&w2h, gW2t_hi);
    cudaGetSymbolAddress((void**)&w2l, gW2t_lo);
    cudaGetSymbolAddress((void**)&hhi, gh_hi);
    cudaGetSymbolAddress((void**)&hlo, gh_lo);

    // 1: fused W1+W2 split + routing init
    split_wt_all_kernel<<<dim3(H_DIM / 32, H_DIM / 32, 2 * E_EXP), 256>>>(W1, W2);
    // 2: gate + x split
    gate_kernel<<<(N_TOK * 32 + 255) / 256, 256>>>(x, Wg, bg, gates_out);
    // 3: scatter
    scatter_kernel<<<(N_TOK * TOPK + 255) / 256, 256>>>();
    // 4: GEMM1  (profiled slot)
    dim3 g1(H_DIM / BN, SLOTS / BM);   // (16, 72)
    mma_gemm_kernel<D_IN, H_DIM, true, true, false>
        <<<g1, 256, SMEM_BYTES>>>(xhi, xlo, w1h, w1l, b1);
    // 5: GEMM2
    dim3 g2(D_IN / BN, SLOTS / BM);    // (4, 72)
    mma_gemm_kernel<H_DIM, D_IN, false, false, true>
        <<<g2, 256, SMEM_BYTES>>>(hhi, hlo, w2h, w2l, b2);
    // 6: combine
    combine_kernel<<<(N_TOK * (D_IN / 4) + 255) / 256, 256>>>(out);
}

// round 11
// speedup vs baseline: 1.1327x; 1.1327x over previous
#include <cuda_runtime.h>
#include <cuda_fp16.h>
#include <math.h>
#include <stdint.h>

#define N_TOK 4096
#define D_IN  512
#define E_EXP 8
#define TOPK  2
#define H_DIM 2048

#define BM 128
#define BN 128
#define BK 32
#define SLOTS (N_TOK*TOPK + E_EXP*BM)   // 9216 padded slots

// smem: 4 planes (Ah, Al, Bh, Bl), each 128 rows x 32 fp16 (64B/row), XOR-swizzled
#define PLANE_BYTES 8192
#define OAH 0
#define OAL 8192
#define OBH 16384
#define OBL 24576
#define STAGE_BYTES 32768
#define NSTAGE 3
#define SMEM_BYTES (NSTAGE * STAGE_BYTES)   // 98304

// -------- scratch (device globals; no allocation allowed) --------
__device__ int   g_counts[E_EXP];
__device__ int   g_cnt2[E_EXP];
__device__ int   g_off[E_EXP + 1];
__device__ int   g_slot_tok[SLOTS];
__device__ float g_slot_w[SLOTS];
__device__ int   g_tok_slot[N_TOK * TOPK];
__device__ float g_topw[N_TOK * TOPK];
__device__ int   g_topi[N_TOK * TOPK];

__device__ __half gx_hi[(size_t)N_TOK * D_IN];
__device__ __half gx_lo[(size_t)N_TOK * D_IN];
__device__ __half gW1t_hi[(size_t)E_EXP * H_DIM * D_IN]; // [e][n][k]
__device__ __half gW1t_lo[(size_t)E_EXP * H_DIM * D_IN];
__device__ __half gW2t_hi[(size_t)E_EXP * D_IN * H_DIM]; // [e][n][k]
__device__ __half gW2t_lo[(size_t)E_EXP * D_IN * H_DIM];
__device__ __half gh_hi[(size_t)SLOTS * H_DIM];
__device__ __half gh_lo[(size_t)SLOTS * H_DIM];
__device__ float g_ybuf[(size_t)SLOTS * D_IN];

// -------- helpers --------
__device__ __forceinline__ void cp16(uint32_t dst, const void* src, int srcBytes) {
    asm volatile("cp.async.cg.shared.global [%0], [%1], 16, %2;"
                 :: "r"(dst), "l"(src), "r"(srcBytes) : "memory");
}
__device__ __forceinline__ void cp_commit() {
    asm volatile("cp.async.commit_group;" ::: "memory");
}
template<int N> __device__ __forceinline__ void cp_wait() {
    asm volatile("cp.async.wait_group %0;" :: "n"(N) : "memory");
}
__device__ __forceinline__ void ldsm4(uint32_t* r, uint32_t addr) {
    asm volatile("ldmatrix.sync.aligned.m8n8.x4.shared.b16 {%0,%1,%2,%3}, [%4];"
                 : "=r"(r[0]), "=r"(r[1]), "=r"(r[2]), "=r"(r[3]) : "r"(addr));
}
__device__ __forceinline__ void mma_f16(float d[4],
                                        uint32_t a0, uint32_t a1, uint32_t a2, uint32_t a3,
                                        uint32_t b0, uint32_t b1) {
    asm volatile(
        "mma.sync.aligned.m16n8k16.row.col.f32.f16.f16.f32 "
        "{%0,%1,%2,%3},{%4,%5,%6,%7},{%8,%9},{%0,%1,%2,%3};"
        : "+f"(d[0]), "+f"(d[1]), "+f"(d[2]), "+f"(d[3])
        : "r"(a0), "r"(a1), "r"(a2), "r"(a3), "r"(b0), "r"(b1));
}
// swizzled byte offset of 16B chunk c (0..3) in row r of a plane
__device__ __forceinline__ uint32_t swz(int r, int c) {
    return (uint32_t)(r * 64 + ((c ^ ((r >> 1) & 3)) * 16));
}
__device__ __forceinline__ uint32_t pack2h(float a, float b) {
    __half2 h = __halves2half2(__float2half(a), __float2half(b));
    return *(uint32_t*)&h;
}

// -------- 1: fused W1+W2 transpose/split + routing-state init --------
__global__ void split_wt_all_kernel(const float* __restrict__ W1,
                                    const float* __restrict__ W2) {
    if (blockIdx.z == 0 && blockIdx.y == 0) {
        int idx = blockIdx.x * blockDim.x + threadIdx.x;
        if (idx < SLOTS) g_slot_tok[idx] = -1;
        if (idx < E_EXP) { g_counts[idx] = 0; g_cnt2[idx] = 0; }
    }
    int z = blockIdx.z;
    const float* src; __half *dhi, *dlo; int K, N, e;
    if (z < E_EXP) { e = z;         src = W1; dhi = gW1t_hi; dlo = gW1t_lo; K = D_IN;  N = H_DIM; }
    else           { e = z - E_EXP; src = W2; dhi = gW2t_hi; dlo = gW2t_lo; K = H_DIM; N = D_IN;  }
    int n0 = blockIdx.x * 32, k0 = blockIdx.y * 32;
    if (n0 >= N || k0 >= K) return;

    __shared__ float t[32][33];
    const float* s = src + (size_t)e * K * N;
    int tx = threadIdx.x & 31, ty = threadIdx.x >> 5;
#pragma unroll
    for (int i = 0; i < 4; i++)
        t[ty + 8 * i][tx] = s[(size_t)(k0 + ty + 8 * i) * N + n0 + tx];
    __syncthreads();
    size_t ob = (size_t)e * K * N;
#pragma unroll
    for (int i = 0; i < 4; i++) {
        int n = n0 + ty + 8 * i, k = k0 + tx;
        float v = t[tx][ty + 8 * i];
        __half h = __float2half(v);
        dhi[ob + (size_t)n * K + k] = h;
        dlo[ob + (size_t)n * K + k] = __float2half(v - __half2float(h));
    }
}

// -------- 2: gating + x hi/lo split (one warp per token) --------
__global__ void gate_kernel(const float* __restrict__ x,
                            const float* __restrict__ Wg,
                            const float* __restrict__ bg,
                            float* __restrict__ gates_out) {
    int t    = (blockIdx.x * blockDim.x + threadIdx.x) >> 5;
    int lane = threadIdx.x & 31;
    if (t >= N_TOK) return;
    const float* xr = x + (size_t)t * D_IN;

    float acc[E_EXP];
#pragma unroll
    for (int e = 0; e < E_EXP; e++) acc[e] = 0.f;
#pragma unroll
    for (int i = 0; i < 4; i++) {
        int d0 = i * 128 + lane * 4;
        float4 xv = *(const float4*)(xr + d0);
        float hx = __half2float(__float2half(xv.x));
        float hy = __half2float(__float2half(xv.y));
        float hz = __half2float(__float2half(xv.z));
        float hw = __half2float(__float2half(xv.w));
        uint32_t h0 = pack2h(xv.x, xv.y), h1 = pack2h(xv.z, xv.w);
        uint32_t l0 = pack2h(xv.x - hx, xv.y - hy);
        uint32_t l1 = pack2h(xv.z - hz, xv.w - hw);
        size_t o = (size_t)t * D_IN + d0;
        *(uint2*)(gx_hi + o) = make_uint2(h0, h1);
        *(uint2*)(gx_lo + o) = make_uint2(l0, l1);
        float xs[4] = {xv.x, xv.y, xv.z, xv.w};
#pragma unroll
        for (int j = 0; j < 4; j++) {
            const float4* wr = (const float4*)(Wg + (d0 + j) * E_EXP);
            float4 w0 = wr[0], w1 = wr[1];
            acc[0] = fmaf(xs[j], w0.x, acc[0]); acc[1] = fmaf(xs[j], w0.y, acc[1]);
            acc[2] = fmaf(xs[j], w0.z, acc[2]); acc[3] = fmaf(xs[j], w0.w, acc[3]);
            acc[4] = fmaf(xs[j], w1.x, acc[4]); acc[5] = fmaf(xs[j], w1.y, acc[5]);
            acc[6] = fmaf(xs[j], w1.z, acc[6]); acc[7] = fmaf(xs[j], w1.w, acc[7]);
        }
    }
#pragma unroll
    for (int o = 16; o > 0; o >>= 1) {
#pragma unroll
        for (int e = 0; e < E_EXP; e++)
            acc[e] += __shfl_xor_sync(0xffffffffu, acc[e], o);
    }
    if (lane == 0) {
        float l[E_EXP], p[E_EXP];
        float m = -1e30f;
#pragma unroll
        for (int e = 0; e < E_EXP; e++) { l[e] = acc[e] + bg[e]; m = fmaxf(m, l[e]); }
        float s = 0.f;
#pragma unroll
        for (int e = 0; e < E_EXP; e++) { p[e] = __expf(l[e] - m); s += p[e]; }
        float inv = 1.f / s;
#pragma unroll
        for (int e = 0; e < E_EXP; e++) p[e] *= inv;
        if (gates_out) {
#pragma unroll
            for (int e = 0; e < E_EXP; e++) gates_out[t * E_EXP + e] = p[e];
        }
        int i1 = 0; float p1 = p[0];
#pragma unroll
        for (int e = 1; e < E_EXP; e++) if (p[e] > p1) { p1 = p[e]; i1 = e; }
        int i2 = -1; float p2 = -1.f;
#pragma unroll
        for (int e = 0; e < E_EXP; e++) if (e != i1 && p[e] > p2) { p2 = p[e]; i2 = e; }
        g_topw[t * 2 + 0] = p1;  g_topi[t * 2 + 0] = i1;
        g_topw[t * 2 + 1] = p2;  g_topi[t * 2 + 1] = i2;
        atomicAdd(&g_counts[i1], 1);
        atomicAdd(&g_counts[i2], 1);
    }
}

// -------- 3: scatter (scan folded in) --------
__global__ void scatter_kernel() {
    __shared__ int soff[E_EXP + 1];
    if (threadIdx.x == 0) {
        int o = 0;
#pragma unroll
        for (int e = 0; e < E_EXP; e++) {
            soff[e] = o;
            o += ((g_counts[e] + BM - 1) / BM) * BM;
        }
        soff[E_EXP] = o;
        if (blockIdx.x == 0) {
#pragma unroll
            for (int e = 0; e <= E_EXP; e++) g_off[e] = soff[e];
        }
    }
    __syncthreads();
    int i = blockIdx.x * blockDim.x + threadIdx.x;
    if (i >= N_TOK * TOPK) return;
    int e = g_topi[i];
    int pos = soff[e] + atomicAdd(&g_cnt2[e], 1);
    g_slot_tok[pos] = i >> 1;
    g_slot_w[pos]   = g_topw[i];
    g_tok_slot[i]   = pos;
}

// -------- grouped fp16 compensated GEMM --------
// NPASS=2: D = Ah*Bh + Al*Bh  (A fully represented, B fp16-rounded)
// NPASS=3: D = Ah*Bh + Al*Bh + Ah*Bl
template<int KTOT, int NTOT, int NPASS, bool GATHER, bool RELU, bool SCALE>
__global__ void __launch_bounds__(256, 2)
mma_gemm_kernel(const __half* __restrict__ Ahi,
                const __half* __restrict__ Alo,
                const __half* __restrict__ Bthi,
                const __half* __restrict__ Btlo,
                const float* __restrict__ Bias)
{
    constexpr int KT = KTOT / BK;
    extern __shared__ char smem[];
    __shared__ int   sTok[BM];
    __shared__ float sW[BM];

    const int m0 = blockIdx.y * BM;
    const int n0 = blockIdx.x * BN;
    if (m0 >= g_off[E_EXP]) return;
    int e = 0;
#pragma unroll
    for (int i = 1; i < E_EXP; i++) if (m0 >= g_off[i]) e = i;

    const int tid = threadIdx.x;
    if (tid < BM) {
        if (GATHER) sTok[tid] = g_slot_tok[m0 + tid];
        if (SCALE)  sW[tid]   = g_slot_w[m0 + tid];
    }
    __syncthreads();

    const __half* Wh = Bthi + (size_t)e * NTOT * KTOT;
    const __half* Wl = Btlo + (size_t)e * NTOT * KTOT;

    const int srow = tid >> 1;
    const int skoff = (tid & 1) * 16;

    const __half *arow_h, *arow_l;
    int abytes = 16;
    if (GATHER) {
        int tok = sTok[srow];
        if (tok >= 0) {
            arow_h = Ahi + (size_t)tok * KTOT + skoff;
            arow_l = Alo + (size_t)tok * KTOT + skoff;
        } else { arow_h = Ahi; arow_l = Alo; abytes = 0; }
    } else {
        arow_h = Ahi + (size_t)(m0 + srow) * KTOT + skoff;
        arow_l = Alo + (size_t)(m0 + srow) * KTOT + skoff;
    }
    const __half* brow_h = Wh + (size_t)(n0 + srow) * KTOT + skoff;
    const __half* brow_l = Wl + (size_t)(n0 + srow) * KTOT + skoff;

    const uint32_t sbase = (uint32_t)__cvta_generic_to_shared(smem);
    const uint32_t d0 = swz(srow, 2 * (tid & 1));
    const uint32_t d1 = swz(srow, 2 * (tid & 1) + 1);

    auto stage = [&](int buf, int k0) {
        uint32_t sb = sbase + buf * STAGE_BYTES;
        cp16(sb + OAH + d0, arow_h + k0,     abytes);
        cp16(sb + OAH + d1, arow_h + k0 + 8, abytes);
        cp16(sb + OAL + d0, arow_l + k0,     abytes);
        cp16(sb + OAL + d1, arow_l + k0 + 8, abytes);
        cp16(sb + OBH + d0, brow_h + k0,     16);
        cp16(sb + OBH + d1, brow_h + k0 + 8, 16);
        if (NPASS == 3) {
            cp16(sb + OBL + d0, brow_l + k0,     16);
            cp16(sb + OBL + d1, brow_l + k0 + 8, 16);
        }
        cp_commit();
    };

    const int lane = tid & 31;
    const int wm = (tid >> 5) >> 2;  // 0..1
    const int wn = (tid >> 5) & 3;   // 0..3
    const int g  = lane >> 3;
    const int lr = lane & 7;

    const int arow0 = wm * 64 + lr + (g & 1) * 8;
    const uint32_t aswz = ((uint32_t)(arow0 >> 1) & 3);
    uint32_t aoff[2];
#pragma unroll
    for (int ks = 0; ks < 2; ks++)
        aoff[ks] = (uint32_t)(arow0 * 64) + (((uint32_t)(ks * 2 + (g >> 1)) ^ aswz) * 16);

    const int brow0 = wn * 32 + lr + ((g >> 1) & 1) * 8;
    const uint32_t bswz = ((uint32_t)(brow0 >> 1) & 3);
    uint32_t boff[2];
#pragma unroll
    for (int ks = 0; ks < 2; ks++)
        boff[ks] = (uint32_t)(brow0 * 64) + (((uint32_t)(ks * 2 + (g & 1)) ^ bswz) * 16);

    float acc[4][4][4];
#pragma unroll
    for (int mt = 0; mt < 4; mt++)
#pragma unroll
        for (int nt = 0; nt < 4; nt++)
#pragma unroll
            for (int i = 0; i < 4; i++) acc[mt][nt][i] = 0.f;

    stage(0, 0);
    stage(1, BK);
    int buf = 0;
    for (int kt = 0; kt < KT; kt++) {
        if (kt < KT - 1) cp_wait<1>(); else cp_wait<0>();
        __syncthreads();
        if (kt + 2 < KT) {
            int nb = buf + 2; if (nb >= NSTAGE) nb -= NSTAGE;
            stage(nb, (kt + 2) * BK);
        }
        const uint32_t sb = sbase + buf * STAGE_BYTES;
#pragma unroll
        for (int ks = 0; ks < 2; ks++) {
            uint32_t bh[8];
#pragma unroll
            for (int np = 0; np < 2; np++)
                ldsm4(&bh[np * 4], sb + OBH + boff[ks] + np * 1024);
            uint32_t ah[4][4];
#pragma unroll
            for (int mt = 0; mt < 4; mt++)
                ldsm4(ah[mt], sb + OAH + aoff[ks] + mt * 1024);
            // pass 1: ah x bh
#pragma unroll
            for (int mt = 0; mt < 4; mt++)
#pragma unroll
                for (int nt = 0; nt < 4; nt++) {
                    int i0 = (nt >> 1) * 4 + (nt & 1) * 2;
                    mma_f16(acc[mt][nt], ah[mt][0], ah[mt][1], ah[mt][2], ah[mt][3],
                            bh[i0], bh[i0 + 1]);
                }
            // pass 2: al x bh
            uint32_t al[4][4];
#pragma unroll
            for (int mt = 0; mt < 4; mt++)
                ldsm4(al[mt], sb + OAL + aoff[ks] + mt * 1024);
#pragma unroll
            for (int mt = 0; mt < 4; mt++)
#pragma unroll
                for (int nt = 0; nt < 4; nt++) {
                    int i0 = (nt >> 1) * 4 + (nt & 1) * 2;
                    mma_f16(acc[mt][nt], al[mt][0], al[mt][1], al[mt][2], al[mt][3],
                            bh[i0], bh[i0 + 1]);
                }
            // pass 3: ah x bl
            if (NPASS == 3) {
                uint32_t bl[8];
#pragma unroll
                for (int np = 0; np < 2; np++)
                    ldsm4(&bl[np * 4], sb + OBL + boff[ks] + np * 1024);
#pragma unroll
                for (int mt = 0; mt < 4; mt++)
#pragma unroll
                    for (int nt = 0; nt < 4; nt++) {
                        int i0 = (nt >> 1) * 4 + (nt & 1) * 2;
                        mma_f16(acc[mt][nt], ah[mt][0], ah[mt][1], ah[mt][2], ah[mt][3],
                                bl[i0], bl[i0 + 1]);
                    }
            }
        }
        buf++; if (buf >= NSTAGE) buf = 0;
    }

    const int r = lane >> 2;
    const int c = lane & 3;
    const float* bias = Bias + (size_t)e * NTOT;
#pragma unroll
    for (int mt = 0; mt < 4; mt++) {
        int row0 = m0 + wm * 64 + mt * 16 + r;
        int lrow = wm * 64 + mt * 16 + r;
#pragma unroll
        for (int nt = 0; nt < 4; nt++) {
            int col = n0 + wn * 32 + nt * 8 + 2 * c;
            float b0v = bias[col], b1v = bias[col + 1];
            float v0 = acc[mt][nt][0] + b0v, v1 = acc[mt][nt][1] + b1v;
            float v2 = acc[mt][nt][2] + b0v, v3 = acc[mt][nt][3] + b1v;
            if (RELU) {
                v0 = fmaxf(v0, 0.f); v1 = fmaxf(v1, 0.f);
                v2 = fmaxf(v2, 0.f); v3 = fmaxf(v3, 0.f);
                size_t o0 = (size_t)row0 * NTOT + col;
                size_t o2 = o0 + (size_t)8 * NTOT;
                __half h;
                h = __float2half(v0); gh_hi[o0]     = h; gh_lo[o0]     = __float2half(v0 - __half2float(h));
                h = __float2half(v1); gh_hi[o0 + 1] = h; gh_lo[o0 + 1] = __float2half(v1 - __half2float(h));
                h = __float2half(v2); gh_hi[o2]     = h; gh_lo[o2]     = __float2half(v2 - __half2float(h));
                h = __float2half(v3); gh_hi[o2 + 1] = h; gh_lo[o2 + 1] = __float2half(v3 - __half2float(h));
            } else {
                float w0 = SCALE ? sW[lrow]     : 1.f;
                float w1 = SCALE ? sW[lrow + 8] : 1.f;
                float* o0 = g_ybuf + (size_t)row0 * NTOT + col;
                *(float2*)o0 = make_float2(v0 * w0, v1 * w0);
                *(float2*)(o0 + (size_t)8 * NTOT) = make_float2(v2 * w1, v3 * w1);
            }
        }
    }
}

// -------- 6: deterministic combine --------
__global__ void combine_kernel(float* __restrict__ out) {
    int i = blockIdx.x * blockDim.x + threadIdx.x;
    if (i >= N_TOK * (D_IN / 4)) return;
    int t  = i >> 7;
    int dd = (i & 127) << 2;
    int s0 = g_tok_slot[t * 2 + 0];
    int s1 = g_tok_slot[t * 2 + 1];
    float4 a = *(const float4*)(g_ybuf + (size_t)s0 * D_IN + dd);
    float4 b = *(const float4*)(g_ybuf + (size_t)s1 * D_IN + dd);
    float4 r = make_float4(a.x + b.x, a.y + b.y, a.z + b.z, a.w + b.w);
    *(float4*)(out + (size_t)t * D_IN + dd) = r;
}

extern "C" void kernel_launch(void* const* d_in, const int* in_sizes, int n_in,
                              void* d_out, int out_size) {
    const float* x  = (const float*)d_in[0];
    const float* Wg = (const float*)d_in[1];
    const float* bg = (const float*)d_in[2];
    const float* W1 = (const float*)d_in[3];
    const float* b1 = (const float*)d_in[4];
    const float* W2 = (const float*)d_in[5];
    const float* b2 = (const float*)d_in[6];
    float* out = (float*)d_out;

    float* gates_out = nullptr;
    if (out_size >= N_TOK * D_IN + N_TOK * E_EXP)
        gates_out = out + (size_t)N_TOK * D_IN;

    cudaFuncSetAttribute(mma_gemm_kernel<D_IN, H_DIM, 2, true, true, false>,
                         cudaFuncAttributeMaxDynamicSharedMemorySize, SMEM_BYTES);
    cudaFuncSetAttribute(mma_gemm_kernel<H_DIM, D_IN, 3, false, false, true>,
                         cudaFuncAttributeMaxDynamicSharedMemorySize, SMEM_BYTES);

    __half *xhi, *xlo, *w1h, *w1l, *w2h, *w2l, *hhi, *hlo;
    cudaGetSymbolAddress((void**)&xhi, gx_hi);
    cudaGetSymbolAddress((void**)&xlo, gx_lo);
    cudaGetSymbolAddress((void**)&w1h, gW1t_hi);
    cudaGetSymbolAddress((void**)&w1l, gW1t_lo);
    cudaGetSymbolAddress((void**)&w2h, gW2t_hi);
    cudaGetSymbolAddress((void**)&w2l, gW2t_lo);
    cudaGetSymbolAddress((void**)&hhi, gh_hi);
    cudaGetSymbolAddress((void**)&hlo, gh_lo);

    // 1: fused W1+W2 split + routing init
    split_wt_all_kernel<<<dim3(H_DIM / 32, H_DIM / 32, 2 * E_EXP), 256>>>(W1, W2);
    // 2: gate + x split
    gate_kernel<<<(N_TOK * 32 + 255) / 256, 256>>>(x, Wg, bg, gates_out);
    // 3: scatter
    scatter_kernel<<<(N_TOK * TOPK + 255) / 256, 256>>>();
    // 4: GEMM1 (2-pass, profiled slot)
    dim3 g1(H_DIM / BN, SLOTS / BM);   // (16, 72)
    mma_gemm_kernel<D_IN, H_DIM, 2, true, true, false>
        <<<g1, 256, SMEM_BYTES>>>(xhi, xlo, w1h, w1l, b1);
    // 5: GEMM2 (3-pass)
    dim3 g2(D_IN / BN, SLOTS / BM);    // (4, 72)
    mma_gemm_kernel<H_DIM, D_IN, 3, false, false, true>
        <<<g2, 256, SMEM_BYTES>>>(hhi, hlo, w2h, w2l, b2);
    // 6: combine
    combine_kernel<<<(N_TOK * (D_IN / 4) + 255) / 256, 256>>>(out);
}

// round 12
// speedup vs baseline: 1.2917x; 1.1404x over previous
#include <cuda_runtime.h>
#include <cuda_fp16.h>
#include <math.h>
#include <stdint.h>

#define N_TOK 4096
#define D_IN  512
#define E_EXP 8
#define TOPK  2
#define H_DIM 2048

#define BM 128
#define BN 128
#define BK 32
#define SLOTS (N_TOK*TOPK + E_EXP*BM)   // 9216 padded slots

// smem: 3 planes (Ah, Al, Bh), each 128 rows x 32 fp16 (64B/row), XOR-swizzled
#define PLANE_BYTES 8192
#define OAH 0
#define OAL 8192
#define OBH 16384
#define STAGE_BYTES 24576
#define NSTAGE 3
#define SMEM_BYTES (NSTAGE * STAGE_BYTES)   // 73728

// -------- scratch (device globals; no allocation allowed) --------
__device__ int   g_counts[E_EXP];
__device__ int   g_cnt2[E_EXP];
__device__ int   g_off[E_EXP + 1];
__device__ int   g_slot_tok[SLOTS];
__device__ float g_slot_w[SLOTS];
__device__ int   g_tok_slot[N_TOK * TOPK];
__device__ float g_topw[N_TOK * TOPK];
__device__ int   g_topi[N_TOK * TOPK];

__device__ __half gx_hi[(size_t)N_TOK * D_IN];
__device__ __half gx_lo[(size_t)N_TOK * D_IN];
__device__ __half gW1t_hi[(size_t)E_EXP * H_DIM * D_IN]; // [e][n][k]
__device__ __half gW2t_hi[(size_t)E_EXP * D_IN * H_DIM]; // [e][n][k]
__device__ __half gh_hi[(size_t)SLOTS * H_DIM];
__device__ __half gh_lo[(size_t)SLOTS * H_DIM];
__device__ float g_ybuf[(size_t)SLOTS * D_IN];

// -------- helpers --------
__device__ __forceinline__ void cp16(uint32_t dst, const void* src, int srcBytes) {
    asm volatile("cp.async.cg.shared.global [%0], [%1], 16, %2;"
                 :: "r"(dst), "l"(src), "r"(srcBytes) : "memory");
}
__device__ __forceinline__ void cp_commit() {
    asm volatile("cp.async.commit_group;" ::: "memory");
}
template<int N> __device__ __forceinline__ void cp_wait() {
    asm volatile("cp.async.wait_group %0;" :: "n"(N) : "memory");
}
__device__ __forceinline__ void ldsm4(uint32_t* r, uint32_t addr) {
    asm volatile("ldmatrix.sync.aligned.m8n8.x4.shared.b16 {%0,%1,%2,%3}, [%4];"
                 : "=r"(r[0]), "=r"(r[1]), "=r"(r[2]), "=r"(r[3]) : "r"(addr));
}
__device__ __forceinline__ void mma_f16(float d[4],
                                        uint32_t a0, uint32_t a1, uint32_t a2, uint32_t a3,
                                        uint32_t b0, uint32_t b1) {
    asm volatile(
        "mma.sync.aligned.m16n8k16.row.col.f32.f16.f16.f32 "
        "{%0,%1,%2,%3},{%4,%5,%6,%7},{%8,%9},{%0,%1,%2,%3};"
        : "+f"(d[0]), "+f"(d[1]), "+f"(d[2]), "+f"(d[3])
        : "r"(a0), "r"(a1), "r"(a2), "r"(a3), "r"(b0), "r"(b1));
}
// swizzled byte offset of 16B chunk c (0..3) in row r of a plane
__device__ __forceinline__ uint32_t swz(int r, int c) {
    return (uint32_t)(r * 64 + ((c ^ ((r >> 1) & 3)) * 16));
}
__device__ __forceinline__ uint32_t pack2h(float a, float b) {
    __half2 h = __halves2half2(__float2half(a), __float2half(b));
    return *(uint32_t*)&h;
}

// -------- 1: fused W1+W2 transpose (fp16 hi only) + routing-state init --------
__global__ void split_wt_all_kernel(const float* __restrict__ W1,
                                    const float* __restrict__ W2) {
    if (blockIdx.z == 0 && blockIdx.y == 0) {
        int idx = blockIdx.x * blockDim.x + threadIdx.x;
        if (idx < SLOTS) g_slot_tok[idx] = -1;
        if (idx < E_EXP) { g_counts[idx] = 0; g_cnt2[idx] = 0; }
    }
    int z = blockIdx.z;
    const float* src; __half* dhi; int K, N, e;
    if (z < E_EXP) { e = z;         src = W1; dhi = gW1t_hi; K = D_IN;  N = H_DIM; }
    else           { e = z - E_EXP; src = W2; dhi = gW2t_hi; K = H_DIM; N = D_IN;  }
    int n0 = blockIdx.x * 32, k0 = blockIdx.y * 32;
    if (n0 >= N || k0 >= K) return;

    __shared__ float t[32][33];
    const float* s = src + (size_t)e * K * N;
    int tx = threadIdx.x & 31, ty = threadIdx.x >> 5;
#pragma unroll
    for (int i = 0; i < 4; i++)
        t[ty + 8 * i][tx] = s[(size_t)(k0 + ty + 8 * i) * N + n0 + tx];
    __syncthreads();
    size_t ob = (size_t)e * K * N;
#pragma unroll
    for (int i = 0; i < 4; i++) {
        int n = n0 + ty + 8 * i, k = k0 + tx;
        dhi[ob + (size_t)n * K + k] = __float2half(t[tx][ty + 8 * i]);
    }
}

// -------- 2: gating + x hi/lo split (one warp per token) --------
__global__ void gate_kernel(const float* __restrict__ x,
                            const float* __restrict__ Wg,
                            const float* __restrict__ bg,
                            float* __restrict__ gates_out) {
    int t    = (blockIdx.x * blockDim.x + threadIdx.x) >> 5;
    int lane = threadIdx.x & 31;
    if (t >= N_TOK) return;
    const float* xr = x + (size_t)t * D_IN;

    float acc[E_EXP];
#pragma unroll
    for (int e = 0; e < E_EXP; e++) acc[e] = 0.f;
#pragma unroll
    for (int i = 0; i < 4; i++) {
        int d0 = i * 128 + lane * 4;
        float4 xv = *(const float4*)(xr + d0);
        float hx = __half2float(__float2half(xv.x));
        float hy = __half2float(__float2half(xv.y));
        float hz = __half2float(__float2half(xv.z));
        float hw = __half2float(__float2half(xv.w));
        uint32_t h0 = pack2h(xv.x, xv.y), h1 = pack2h(xv.z, xv.w);
        uint32_t l0 = pack2h(xv.x - hx, xv.y - hy);
        uint32_t l1 = pack2h(xv.z - hz, xv.w - hw);
        size_t o = (size_t)t * D_IN + d0;
        *(uint2*)(gx_hi + o) = make_uint2(h0, h1);
        *(uint2*)(gx_lo + o) = make_uint2(l0, l1);
        float xs[4] = {xv.x, xv.y, xv.z, xv.w};
#pragma unroll
        for (int j = 0; j < 4; j++) {
            const float4* wr = (const float4*)(Wg + (d0 + j) * E_EXP);
            float4 w0 = wr[0], w1 = wr[1];
            acc[0] = fmaf(xs[j], w0.x, acc[0]); acc[1] = fmaf(xs[j], w0.y, acc[1]);
            acc[2] = fmaf(xs[j], w0.z, acc[2]); acc[3] = fmaf(xs[j], w0.w, acc[3]);
            acc[4] = fmaf(xs[j], w1.x, acc[4]); acc[5] = fmaf(xs[j], w1.y, acc[5]);
            acc[6] = fmaf(xs[j], w1.z, acc[6]); acc[7] = fmaf(xs[j], w1.w, acc[7]);
        }
    }
#pragma unroll
    for (int o = 16; o > 0; o >>= 1) {
#pragma unroll
        for (int e = 0; e < E_EXP; e++)
            acc[e] += __shfl_xor_sync(0xffffffffu, acc[e], o);
    }
    if (lane == 0) {
        float l[E_EXP], p[E_EXP];
        float m = -1e30f;
#pragma unroll
        for (int e = 0; e < E_EXP; e++) { l[e] = acc[e] + bg[e]; m = fmaxf(m, l[e]); }
        float s = 0.f;
#pragma unroll
        for (int e = 0; e < E_EXP; e++) { p[e] = __expf(l[e] - m); s += p[e]; }
        float inv = 1.f / s;
#pragma unroll
        for (int e = 0; e < E_EXP; e++) p[e] *= inv;
        if (gates_out) {
#pragma unroll
            for (int e = 0; e < E_EXP; e++) gates_out[t * E_EXP + e] = p[e];
        }
        int i1 = 0; float p1 = p[0];
#pragma unroll
        for (int e = 1; e < E_EXP; e++) if (p[e] > p1) { p1 = p[e]; i1 = e; }
        int i2 = -1; float p2 = -1.f;
#pragma unroll
        for (int e = 0; e < E_EXP; e++) if (e != i1 && p[e] > p2) { p2 = p[e]; i2 = e; }
        g_topw[t * 2 + 0] = p1;  g_topi[t * 2 + 0] = i1;
        g_topw[t * 2 + 1] = p2;  g_topi[t * 2 + 1] = i2;
        atomicAdd(&g_counts[i1], 1);
        atomicAdd(&g_counts[i2], 1);
    }
}

// -------- 3: scatter (scan folded in) --------
__global__ void scatter_kernel() {
    __shared__ int soff[E_EXP + 1];
    if (threadIdx.x == 0) {
        int o = 0;
#pragma unroll
        for (int e = 0; e < E_EXP; e++) {
            soff[e] = o;
            o += ((g_counts[e] + BM - 1) / BM) * BM;
        }
        soff[E_EXP] = o;
        if (blockIdx.x == 0) {
#pragma unroll
            for (int e = 0; e <= E_EXP; e++) g_off[e] = soff[e];
        }
    }
    __syncthreads();
    int i = blockIdx.x * blockDim.x + threadIdx.x;
    if (i >= N_TOK * TOPK) return;
    int e = g_topi[i];
    int pos = soff[e] + atomicAdd(&g_cnt2[e], 1);
    g_slot_tok[pos] = i >> 1;
    g_slot_w[pos]   = g_topw[i];
    g_tok_slot[i]   = pos;
}

// -------- grouped fp16 2-pass compensated GEMM: D = (Ah+Al) x Bh --------
template<int KTOT, int NTOT, bool GATHER, bool RELU, bool SCALE>
__global__ void __launch_bounds__(256, 2)
mma_gemm_kernel(const __half* __restrict__ Ahi,
                const __half* __restrict__ Alo,
                const __half* __restrict__ Bthi,
                const float* __restrict__ Bias)
{
    constexpr int KT = KTOT / BK;
    extern __shared__ char smem[];
    __shared__ int   sTok[BM];
    __shared__ float sW[BM];

    const int m0 = blockIdx.y * BM;
    const int n0 = blockIdx.x * BN;
    if (m0 >= g_off[E_EXP]) return;
    int e = 0;
#pragma unroll
    for (int i = 1; i < E_EXP; i++) if (m0 >= g_off[i]) e = i;

    const int tid = threadIdx.x;
    if (tid < BM) {
        if (GATHER) sTok[tid] = g_slot_tok[m0 + tid];
        if (SCALE)  sW[tid]   = g_slot_w[m0 + tid];
    }
    __syncthreads();

    const __half* Wh = Bthi + (size_t)e * NTOT * KTOT;

    const int srow = tid >> 1;
    const int skoff = (tid & 1) * 16;

    const __half *arow_h, *arow_l;
    int abytes = 16;
    if (GATHER) {
        int tok = sTok[srow];
        if (tok >= 0) {
            arow_h = Ahi + (size_t)tok * KTOT + skoff;
            arow_l = Alo + (size_t)tok * KTOT + skoff;
        } else { arow_h = Ahi; arow_l = Alo; abytes = 0; }
    } else {
        arow_h = Ahi + (size_t)(m0 + srow) * KTOT + skoff;
        arow_l = Alo + (size_t)(m0 + srow) * KTOT + skoff;
    }
    const __half* brow_h = Wh + (size_t)(n0 + srow) * KTOT + skoff;

    const uint32_t sbase = (uint32_t)__cvta_generic_to_shared(smem);
    const uint32_t d0 = swz(srow, 2 * (tid & 1));
    const uint32_t d1 = swz(srow, 2 * (tid & 1) + 1);

    auto stage = [&](int buf, int k0) {
        uint32_t sb = sbase + buf * STAGE_BYTES;
        cp16(sb + OAH + d0, arow_h + k0,     abytes);
        cp16(sb + OAH + d1, arow_h + k0 + 8, abytes);
        cp16(sb + OAL + d0, arow_l + k0,     abytes);
        cp16(sb + OAL + d1, arow_l + k0 + 8, abytes);
        cp16(sb + OBH + d0, brow_h + k0,     16);
        cp16(sb + OBH + d1, brow_h + k0 + 8, 16);
        cp_commit();
    };

    const int lane = tid & 31;
    const int wm = (tid >> 5) >> 2;  // 0..1
    const int wn = (tid >> 5) & 3;   // 0..3
    const int g  = lane >> 3;
    const int lr = lane & 7;

    const int arow0 = wm * 64 + lr + (g & 1) * 8;
    const uint32_t aswz = ((uint32_t)(arow0 >> 1) & 3);
    uint32_t aoff[2];
#pragma unroll
    for (int ks = 0; ks < 2; ks++)
        aoff[ks] = (uint32_t)(arow0 * 64) + (((uint32_t)(ks * 2 + (g >> 1)) ^ aswz) * 16);

    const int brow0 = wn * 32 + lr + ((g >> 1) & 1) * 8;
    const uint32_t bswz = ((uint32_t)(brow0 >> 1) & 3);
    uint32_t boff[2];
#pragma unroll
    for (int ks = 0; ks < 2; ks++)
        boff[ks] = (uint32_t)(brow0 * 64) + (((uint32_t)(ks * 2 + (g & 1)) ^ bswz) * 16);

    float acc[4][4][4];
#pragma unroll
    for (int mt = 0; mt < 4; mt++)
#pragma unroll
        for (int nt = 0; nt < 4; nt++)
#pragma unroll
            for (int i = 0; i < 4; i++) acc[mt][nt][i] = 0.f;

    stage(0, 0);
    stage(1, BK);
    int buf = 0;
    for (int kt = 0; kt < KT; kt++) {
        if (kt < KT - 1) cp_wait<1>(); else cp_wait<0>();
        __syncthreads();
        if (kt + 2 < KT) {
            int nb = buf + 2; if (nb >= NSTAGE) nb -= NSTAGE;
            stage(nb, (kt + 2) * BK);
        }
        const uint32_t sb = sbase + buf * STAGE_BYTES;
#pragma unroll
        for (int ks = 0; ks < 2; ks++) {
            uint32_t bh[8];
#pragma unroll
            for (int np = 0; np < 2; np++)
                ldsm4(&bh[np * 4], sb + OBH + boff[ks] + np * 1024);
            uint32_t ah[4][4];
#pragma unroll
            for (int mt = 0; mt < 4; mt++)
                ldsm4(ah[mt], sb + OAH + aoff[ks] + mt * 1024);
            // pass 1: ah x bh
#pragma unroll
            for (int mt = 0; mt < 4; mt++)
#pragma unroll
                for (int nt = 0; nt < 4; nt++) {
                    int i0 = (nt >> 1) * 4 + (nt & 1) * 2;
                    mma_f16(acc[mt][nt], ah[mt][0], ah[mt][1], ah[mt][2], ah[mt][3],
                            bh[i0], bh[i0 + 1]);
                }
            // pass 2: al x bh
            uint32_t al[4][4];
#pragma unroll
            for (int mt = 0; mt < 4; mt++)
                ldsm4(al[mt], sb + OAL + aoff[ks] + mt * 1024);
#pragma unroll
            for (int mt = 0; mt < 4; mt++)
#pragma unroll
                for (int nt = 0; nt < 4; nt++) {
                    int i0 = (nt >> 1) * 4 + (nt & 1) * 2;
                    mma_f16(acc[mt][nt], al[mt][0], al[mt][1], al[mt][2], al[mt][3],
                            bh[i0], bh[i0 + 1]);
                }
        }
        buf++; if (buf >= NSTAGE) buf = 0;
    }

    const int r = lane >> 2;
    const int c = lane & 3;
    const float* bias = Bias + (size_t)e * NTOT;
#pragma unroll
    for (int mt = 0; mt < 4; mt++) {
        int row0 = m0 + wm * 64 + mt * 16 + r;
        int lrow = wm * 64 + mt * 16 + r;
#pragma unroll
        for (int nt = 0; nt < 4; nt++) {
            int col = n0 + wn * 32 + nt * 8 + 2 * c;
            float b0v = bias[col], b1v = bias[col + 1];
            float v0 = acc[mt][nt][0] + b0v, v1 = acc[mt][nt][1] + b1v;
            float v2 = acc[mt][nt][2] + b0v, v3 = acc[mt][nt][3] + b1v;
            if (RELU) {
                v0 = fmaxf(v0, 0.f); v1 = fmaxf(v1, 0.f);
                v2 = fmaxf(v2, 0.f); v3 = fmaxf(v3, 0.f);
                size_t o0 = (size_t)row0 * NTOT + col;
                size_t o2 = o0 + (size_t)8 * NTOT;
                __half h;
                h = __float2half(v0); gh_hi[o0]     = h; gh_lo[o0]     = __float2half(v0 - __half2float(h));
                h = __float2half(v1); gh_hi[o0 + 1] = h; gh_lo[o0 + 1] = __float2half(v1 - __half2float(h));
                h = __float2half(v2); gh_hi[o2]     = h; gh_lo[o2]     = __float2half(v2 - __half2float(h));
                h = __float2half(v3); gh_hi[o2 + 1] = h; gh_lo[o2 + 1] = __float2half(v3 - __half2float(h));
            } else {
                float w0 = SCALE ? sW[lrow]     : 1.f;
                float w1 = SCALE ? sW[lrow + 8] : 1.f;
                float* o0 = g_ybuf + (size_t)row0 * NTOT + col;
                *(float2*)o0 = make_float2(v0 * w0, v1 * w0);
                *(float2*)(o0 + (size_t)8 * NTOT) = make_float2(v2 * w1, v3 * w1);
            }
        }
    }
}

// -------- 6: deterministic combine --------
__global__ void combine_kernel(float* __restrict__ out) {
    int i = blockIdx.x * blockDim.x + threadIdx.x;
    if (i >= N_TOK * (D_IN / 4)) return;
    int t  = i >> 7;
    int dd = (i & 127) << 2;
    int s0 = g_tok_slot[t * 2 + 0];
    int s1 = g_tok_slot[t * 2 + 1];
    float4 a = *(const float4*)(g_ybuf + (size_t)s0 * D_IN + dd);
    float4 b = *(const float4*)(g_ybuf + (size_t)s1 * D_IN + dd);
    float4 r = make_float4(a.x + b.x, a.y + b.y, a.z + b.z, a.w + b.w);
    *(float4*)(out + (size_t)t * D_IN + dd) = r;
}

extern "C" void kernel_launch(void* const* d_in, const int* in_sizes, int n_in,
                              void* d_out, int out_size) {
    const float* x  = (const float*)d_in[0];
    const float* Wg = (const float*)d_in[1];
    const float* bg = (const float*)d_in[2];
    const float* W1 = (const float*)d_in[3];
    const float* b1 = (const float*)d_in[4];
    const float* W2 = (const float*)d_in[5];
    const float* b2 = (const float*)d_in[6];
    float* out = (float*)d_out;

    float* gates_out = nullptr;
    if (out_size >= N_TOK * D_IN + N_TOK * E_EXP)
        gates_out = out + (size_t)N_TOK * D_IN;

    cudaFuncSetAttribute(mma_gemm_kernel<D_IN, H_DIM, true, true, false>,
                         cudaFuncAttributeMaxDynamicSharedMemorySize, SMEM_BYTES);
    cudaFuncSetAttribute(mma_gemm_kernel<H_DIM, D_IN, false, false, true>,
                         cudaFuncAttributeMaxDynamicSharedMemorySize, SMEM_BYTES);

    __half *xhi, *xlo, *w1h, *w2h, *hhi, *hlo;
    cudaGetSymbolAddress((void**)&xhi, gx_hi);
    cudaGetSymbolAddress((void**)&xlo, gx_lo);
    cudaGetSymbolAddress((void**)&w1h, gW1t_hi);
    cudaGetSymbolAddress((void**)&w2h, gW2t_hi);
    cudaGetSymbolAddress((void**)&hhi, gh_hi);
    cudaGetSymbolAddress((void**)&hlo, gh_lo);

    // 1: fused W1+W2 transpose (hi only) + routing init
    split_wt_all_kernel<<<dim3(H_DIM / 32, H_DIM / 32, 2 * E_EXP), 256>>>(W1, W2);
    // 2: gate + x split
    gate_kernel<<<(N_TOK * 32 + 255) / 256, 256>>>(x, Wg, bg, gates_out);
    // 3: scatter
    scatter_kernel<<<(N_TOK * TOPK + 255) / 256, 256>>>();
    // 4: GEMM1 (2-pass, profiled slot)
    dim3 g1(H_DIM / BN, SLOTS / BM);   // (16, 72)
    mma_gemm_kernel<D_IN, H_DIM, true, true, false>
        <<<g1, 256, SMEM_BYTES>>>(xhi, xlo, w1h, b1);
    // 5: GEMM2 (2-pass)
    dim3 g2(D_IN / BN, SLOTS / BM);    // (4, 72)
    mma_gemm_kernel<H_DIM, D_IN, false, false, true>
        <<<g2, 256, SMEM_BYTES>>>(hhi, hlo, w2h, b2);
    // 6: combine
    combine_kernel<<<(N_TOK * (D_IN / 4) + 255) / 256, 256>>>(out);
}

// round 13
// speedup vs baseline: 1.3564x; 1.0501x over previous
#include <cuda_runtime.h>
#include <cuda_fp16.h>
#include <math.h>
#include <stdint.h>

#define N_TOK 4096
#define D_IN  512
#define E_EXP 8
#define TOPK  2
#define H_DIM 2048

#define BM 64
#define BN 128
#define BK 32
#define SLOTS (N_TOK*TOPK + E_EXP*BM)   // 8704 padded slots

// smem: Ah[64x32] Al[64x32] Bh[128x32] fp16, 64B rows, XOR-swizzled
#define OAH 0
#define OAL 4096
#define OBH 8192
#define STAGE_BYTES 16384
#define NSTAGE 4
#define SMEM_BYTES (NSTAGE * STAGE_BYTES)   // 65536

// -------- scratch (device globals; no allocation allowed) --------
__device__ int   g_counts[E_EXP];
__device__ int   g_cnt2[E_EXP];
__device__ int   g_off[E_EXP + 1];
__device__ int   g_slot_tok[SLOTS];
__device__ float g_slot_w[SLOTS];
__device__ int   g_tok_slot[N_TOK * TOPK];
__device__ float g_topw[N_TOK * TOPK];
__device__ int   g_topi[N_TOK * TOPK];

__device__ __half gx_hi[(size_t)N_TOK * D_IN];
__device__ __half gx_lo[(size_t)N_TOK * D_IN];
__device__ __half gW1t_hi[(size_t)E_EXP * H_DIM * D_IN]; // [e][n][k]
__device__ __half gW2t_hi[(size_t)E_EXP * D_IN * H_DIM]; // [e][n][k]
__device__ __half gh_hi[(size_t)SLOTS * H_DIM];
__device__ __half gh_lo[(size_t)SLOTS * H_DIM];
__device__ float g_ybuf[(size_t)SLOTS * D_IN];

// -------- helpers --------
__device__ __forceinline__ void cp16(uint32_t dst, const void* src, int srcBytes) {
    asm volatile("cp.async.cg.shared.global [%0], [%1], 16, %2;"
                 :: "r"(dst), "l"(src), "r"(srcBytes) : "memory");
}
__device__ __forceinline__ void cp_commit() {
    asm volatile("cp.async.commit_group;" ::: "memory");
}
template<int N> __device__ __forceinline__ void cp_wait() {
    asm volatile("cp.async.wait_group %0;" :: "n"(N) : "memory");
}
__device__ __forceinline__ void ldsm4(uint32_t* r, uint32_t addr) {
    asm volatile("ldmatrix.sync.aligned.m8n8.x4.shared.b16 {%0,%1,%2,%3}, [%4];"
                 : "=r"(r[0]), "=r"(r[1]), "=r"(r[2]), "=r"(r[3]) : "r"(addr));
}
__device__ __forceinline__ void mma_f16(float d[4],
                                        uint32_t a0, uint32_t a1, uint32_t a2, uint32_t a3,
                                        uint32_t b0, uint32_t b1) {
    asm volatile(
        "mma.sync.aligned.m16n8k16.row.col.f32.f16.f16.f32 "
        "{%0,%1,%2,%3},{%4,%5,%6,%7},{%8,%9},{%0,%1,%2,%3};"
        : "+f"(d[0]), "+f"(d[1]), "+f"(d[2]), "+f"(d[3])
        : "r"(a0), "r"(a1), "r"(a2), "r"(a3), "r"(b0), "r"(b1));
}
// swizzled byte offset of 16B chunk c (0..3) in 64B row r
__device__ __forceinline__ uint32_t swz(int r, int c) {
    return (uint32_t)(r * 64 + ((c ^ ((r >> 1) & 3)) * 16));
}
__device__ __forceinline__ uint32_t pack2h(float a, float b) {
    __half2 h = __halves2half2(__float2half(a), __float2half(b));
    return *(uint32_t*)&h;
}

// -------- 1: fused W1+W2 transpose (fp16 hi only) + routing-state init --------
__global__ void split_wt_all_kernel(const float* __restrict__ W1,
                                    const float* __restrict__ W2) {
    if (blockIdx.z == 0 && blockIdx.y == 0) {
        int idx = blockIdx.x * blockDim.x + threadIdx.x;
        if (idx < SLOTS) g_slot_tok[idx] = -1;
        if (idx < E_EXP) { g_counts[idx] = 0; g_cnt2[idx] = 0; }
    }
    int z = blockIdx.z;
    const float* src; __half* dhi; int K, N, e;
    if (z < E_EXP) { e = z;         src = W1; dhi = gW1t_hi; K = D_IN;  N = H_DIM; }
    else           { e = z - E_EXP; src = W2; dhi = gW2t_hi; K = H_DIM; N = D_IN;  }
    int n0 = blockIdx.x * 32, k0 = blockIdx.y * 32;
    if (n0 >= N || k0 >= K) return;

    __shared__ float t[32][33];
    const float* s = src + (size_t)e * K * N;
    int tx = threadIdx.x & 31, ty = threadIdx.x >> 5;
#pragma unroll
    for (int i = 0; i < 4; i++)
        t[ty + 8 * i][tx] = s[(size_t)(k0 + ty + 8 * i) * N + n0 + tx];
    __syncthreads();
    size_t ob = (size_t)e * K * N;
#pragma unroll
    for (int i = 0; i < 4; i++) {
        int n = n0 + ty + 8 * i, k = k0 + tx;
        dhi[ob + (size_t)n * K + k] = __float2half(t[tx][ty + 8 * i]);
    }
}

// -------- 2: gating + x hi/lo split (one warp per token) --------
__global__ void gate_kernel(const float* __restrict__ x,
                            const float* __restrict__ Wg,
                            const float* __restrict__ bg,
                            float* __restrict__ gates_out) {
    int t    = (blockIdx.x * blockDim.x + threadIdx.x) >> 5;
    int lane = threadIdx.x & 31;
    if (t >= N_TOK) return;
    const float* xr = x + (size_t)t * D_IN;

    float acc[E_EXP];
#pragma unroll
    for (int e = 0; e < E_EXP; e++) acc[e] = 0.f;
#pragma unroll
    for (int i = 0; i < 4; i++) {
        int d0 = i * 128 + lane * 4;
        float4 xv = *(const float4*)(xr + d0);
        float hx = __half2float(__float2half(xv.x));
        float hy = __half2float(__float2half(xv.y));
        float hz = __half2float(__float2half(xv.z));
        float hw = __half2float(__float2half(xv.w));
        uint32_t h0 = pack2h(xv.x, xv.y), h1 = pack2h(xv.z, xv.w);
        uint32_t l0 = pack2h(xv.x - hx, xv.y - hy);
        uint32_t l1 = pack2h(xv.z - hz, xv.w - hw);
        size_t o = (size_t)t * D_IN + d0;
        *(uint2*)(gx_hi + o) = make_uint2(h0, h1);
        *(uint2*)(gx_lo + o) = make_uint2(l0, l1);
        float xs[4] = {xv.x, xv.y, xv.z, xv.w};
#pragma unroll
        for (int j = 0; j < 4; j++) {
            const float4* wr = (const float4*)(Wg + (d0 + j) * E_EXP);
            float4 w0 = wr[0], w1 = wr[1];
            acc[0] = fmaf(xs[j], w0.x, acc[0]); acc[1] = fmaf(xs[j], w0.y, acc[1]);
            acc[2] = fmaf(xs[j], w0.z, acc[2]); acc[3] = fmaf(xs[j], w0.w, acc[3]);
            acc[4] = fmaf(xs[j], w1.x, acc[4]); acc[5] = fmaf(xs[j], w1.y, acc[5]);
            acc[6] = fmaf(xs[j], w1.z, acc[6]); acc[7] = fmaf(xs[j], w1.w, acc[7]);
        }
    }
#pragma unroll
    for (int o = 16; o > 0; o >>= 1) {
#pragma unroll
        for (int e = 0; e < E_EXP; e++)
            acc[e] += __shfl_xor_sync(0xffffffffu, acc[e], o);
    }
    if (lane == 0) {
        float l[E_EXP], p[E_EXP];
        float m = -1e30f;
#pragma unroll
        for (int e = 0; e < E_EXP; e++) { l[e] = acc[e] + bg[e]; m = fmaxf(m, l[e]); }
        float s = 0.f;
#pragma unroll
        for (int e = 0; e < E_EXP; e++) { p[e] = __expf(l[e] - m); s += p[e]; }
        float inv = 1.f / s;
#pragma unroll
        for (int e = 0; e < E_EXP; e++) p[e] *= inv;
        if (gates_out) {
#pragma unroll
            for (int e = 0; e < E_EXP; e++) gates_out[t * E_EXP + e] = p[e];
        }
        int i1 = 0; float p1 = p[0];
#pragma unroll
        for (int e = 1; e < E_EXP; e++) if (p[e] > p1) { p1 = p[e]; i1 = e; }
        int i2 = -1; float p2 = -1.f;
#pragma unroll
        for (int e = 0; e < E_EXP; e++) if (e != i1 && p[e] > p2) { p2 = p[e]; i2 = e; }
        g_topw[t * 2 + 0] = p1;  g_topi[t * 2 + 0] = i1;
        g_topw[t * 2 + 1] = p2;  g_topi[t * 2 + 1] = i2;
        atomicAdd(&g_counts[i1], 1);
        atomicAdd(&g_counts[i2], 1);
    }
}

// -------- 3: scatter (scan folded in; pads to BM=64) --------
__global__ void scatter_kernel() {
    __shared__ int soff[E_EXP + 1];
    if (threadIdx.x == 0) {
        int o = 0;
#pragma unroll
        for (int e = 0; e < E_EXP; e++) {
            soff[e] = o;
            o += ((g_counts[e] + BM - 1) / BM) * BM;
        }
        soff[E_EXP] = o;
        if (blockIdx.x == 0) {
#pragma unroll
            for (int e = 0; e <= E_EXP; e++) g_off[e] = soff[e];
        }
    }
    __syncthreads();
    int i = blockIdx.x * blockDim.x + threadIdx.x;
    if (i >= N_TOK * TOPK) return;
    int e = g_topi[i];
    int pos = soff[e] + atomicAdd(&g_cnt2[e], 1);
    g_slot_tok[pos] = i >> 1;
    g_slot_w[pos]   = g_topw[i];
    g_tok_slot[i]   = pos;
}

// -------- grouped fp16 2-pass GEMM: CTA 64x128, warp 32x32, 3 CTAs/SM --------
template<int KTOT, int NTOT, bool GATHER, bool RELU, bool SCALE>
__global__ void __launch_bounds__(256, 3)
mma_gemm_kernel(const __half* __restrict__ Ahi,
                const __half* __restrict__ Alo,
                const __half* __restrict__ Bthi,
                const float* __restrict__ Bias)
{
    constexpr int KT = KTOT / BK;
    extern __shared__ char smem[];
    __shared__ int   sTok[BM];
    __shared__ float sW[BM];

    const int m0 = blockIdx.y * BM;
    const int n0 = blockIdx.x * BN;
    if (m0 >= g_off[E_EXP]) return;
    int e = 0;
#pragma unroll
    for (int i = 1; i < E_EXP; i++) if (m0 >= g_off[i]) e = i;

    const int tid = threadIdx.x;
    if (tid < BM) {
        if (GATHER) sTok[tid] = g_slot_tok[m0 + tid];
        if (SCALE)  sW[tid]   = g_slot_w[m0 + tid];
    }
    __syncthreads();

    const __half* Wh = Bthi + (size_t)e * NTOT * KTOT;

    // staging: A rows tid>>2 (chunk tid&3), B rows tid>>1 (chunks 2*(tid&1)+{0,1})
    const int arowi = tid >> 2;
    const int ac    = tid & 3;
    const int browi = tid >> 1;
    const int bc    = (tid & 1) * 2;

    const __half *arow_h, *arow_l;
    int abytes = 16;
    if (GATHER) {
        int tok = sTok[arowi];
        if (tok >= 0) {
            arow_h = Ahi + (size_t)tok * KTOT + ac * 8;
            arow_l = Alo + (size_t)tok * KTOT + ac * 8;
        } else { arow_h = Ahi; arow_l = Alo; abytes = 0; }
    } else {
        arow_h = Ahi + (size_t)(m0 + arowi) * KTOT + ac * 8;
        arow_l = Alo + (size_t)(m0 + arowi) * KTOT + ac * 8;
    }
    const __half* brow_h = Wh + (size_t)(n0 + browi) * KTOT + bc * 8;

    const uint32_t sbase = (uint32_t)__cvta_generic_to_shared(smem);
    const uint32_t da  = swz(arowi, ac);
    const uint32_t db0 = swz(browi, bc);
    const uint32_t db1 = swz(browi, bc + 1);

    auto stage = [&](int buf, int k0) {
        uint32_t sb = sbase + buf * STAGE_BYTES;
        cp16(sb + OAH + da,  arow_h + k0, abytes);
        cp16(sb + OAL + da,  arow_l + k0, abytes);
        cp16(sb + OBH + db0, brow_h + k0, 16);
        cp16(sb + OBH + db1, brow_h + k0 + 8, 16);
        cp_commit();
    };

    const int lane = tid & 31;
    const int wm = (tid >> 5) >> 2;  // 0..1 (32 rows each)
    const int wn = (tid >> 5) & 3;   // 0..3 (32 cols each)
    const int g  = lane >> 3;
    const int lr = lane & 7;

    const int arow0 = wm * 32 + lr + (g & 1) * 8;
    const uint32_t aswz = ((uint32_t)(arow0 >> 1) & 3);
    uint32_t aoff[2];
#pragma unroll
    for (int ks = 0; ks < 2; ks++)
        aoff[ks] = (uint32_t)(arow0 * 64) + (((uint32_t)(ks * 2 + (g >> 1)) ^ aswz) * 16);

    const int brow0 = wn * 32 + lr + ((g >> 1) & 1) * 8;
    const uint32_t bswz = ((uint32_t)(brow0 >> 1) & 3);
    uint32_t boff[2];
#pragma unroll
    for (int ks = 0; ks < 2; ks++)
        boff[ks] = (uint32_t)(brow0 * 64) + (((uint32_t)(ks * 2 + (g & 1)) ^ bswz) * 16);

    float acc[2][4][4];
#pragma unroll
    for (int mt = 0; mt < 2; mt++)
#pragma unroll
        for (int nt = 0; nt < 4; nt++)
#pragma unroll
            for (int i = 0; i < 4; i++) acc[mt][nt][i] = 0.f;

    stage(0, 0);
    stage(1, BK);
    stage(2, 2 * BK);
    int buf = 0;
    for (int kt = 0; kt < KT; kt++) {
        if (kt < KT - 2) cp_wait<2>();
        else if (kt < KT - 1) cp_wait<1>();
        else cp_wait<0>();
        __syncthreads();
        if (kt + 3 < KT) {
            int nb = buf + 3; if (nb >= NSTAGE) nb -= NSTAGE;
            stage(nb, (kt + 3) * BK);
        }
        const uint32_t sb = sbase + buf * STAGE_BYTES;
#pragma unroll
        for (int ks = 0; ks < 2; ks++) {
            uint32_t bh[8];
#pragma unroll
            for (int np = 0; np < 2; np++)
                ldsm4(&bh[np * 4], sb + OBH + boff[ks] + np * 1024);
            uint32_t ah[2][4];
#pragma unroll
            for (int mt = 0; mt < 2; mt++)
                ldsm4(ah[mt], sb + OAH + aoff[ks] + mt * 1024);
            // pass 1: ah x bh
#pragma unroll
            for (int mt = 0; mt < 2; mt++)
#pragma unroll
                for (int nt = 0; nt < 4; nt++) {
                    int i0 = (nt >> 1) * 4 + (nt & 1) * 2;
                    mma_f16(acc[mt][nt], ah[mt][0], ah[mt][1], ah[mt][2], ah[mt][3],
                            bh[i0], bh[i0 + 1]);
                }
            // pass 2: al x bh
            uint32_t al[2][4];
#pragma unroll
            for (int mt = 0; mt < 2; mt++)
                ldsm4(al[mt], sb + OAL + aoff[ks] + mt * 1024);
#pragma unroll
            for (int mt = 0; mt < 2; mt++)
#pragma unroll
                for (int nt = 0; nt < 4; nt++) {
                    int i0 = (nt >> 1) * 4 + (nt & 1) * 2;
                    mma_f16(acc[mt][nt], al[mt][0], al[mt][1], al[mt][2], al[mt][3],
                            bh[i0], bh[i0 + 1]);
                }
        }
        buf++; if (buf >= NSTAGE) buf = 0;
    }

    const int r = lane >> 2;
    const int c = lane & 3;
    const float* bias = Bias + (size_t)e * NTOT;
#pragma unroll
    for (int mt = 0; mt < 2; mt++) {
        int row0 = m0 + wm * 32 + mt * 16 + r;
        int lrow = wm * 32 + mt * 16 + r;
#pragma unroll
        for (int nt = 0; nt < 4; nt++) {
            int col = n0 + wn * 32 + nt * 8 + 2 * c;
            float b0v = bias[col], b1v = bias[col + 1];
            float v0 = acc[mt][nt][0] + b0v, v1 = acc[mt][nt][1] + b1v;
            float v2 = acc[mt][nt][2] + b0v, v3 = acc[mt][nt][3] + b1v;
            if (RELU) {
                v0 = fmaxf(v0, 0.f); v1 = fmaxf(v1, 0.f);
                v2 = fmaxf(v2, 0.f); v3 = fmaxf(v3, 0.f);
                size_t o0 = (size_t)row0 * NTOT + col;
                size_t o2 = o0 + (size_t)8 * NTOT;
                __half h;
                h = __float2half(v0); gh_hi[o0]     = h; gh_lo[o0]     = __float2half(v0 - __half2float(h));
                h = __float2half(v1); gh_hi[o0 + 1] = h; gh_lo[o0 + 1] = __float2half(v1 - __half2float(h));
                h = __float2half(v2); gh_hi[o2]     = h; gh_lo[o2]     = __float2half(v2 - __half2float(h));
                h = __float2half(v3); gh_hi[o2 + 1] = h; gh_lo[o2 + 1] = __float2half(v3 - __half2float(h));
            } else {
                float w0 = SCALE ? sW[lrow]     : 1.f;
                float w1 = SCALE ? sW[lrow + 8] : 1.f;
                float* o0 = g_ybuf + (size_t)row0 * NTOT + col;
                *(float2*)o0 = make_float2(v0 * w0, v1 * w0);
                *(float2*)(o0 + (size_t)8 * NTOT) = make_float2(v2 * w1, v3 * w1);
            }
        }
    }
}

// -------- 6: deterministic combine --------
__global__ void combine_kernel(float* __restrict__ out) {
    int i = blockIdx.x * blockDim.x + threadIdx.x;
    if (i >= N_TOK * (D_IN / 4)) return;
    int t  = i >> 7;
    int dd = (i & 127) << 2;
    int s0 = g_tok_slot[t * 2 + 0];
    int s1 = g_tok_slot[t * 2 + 1];
    float4 a = *(const float4*)(g_ybuf + (size_t)s0 * D_IN + dd);
    float4 b = *(const float4*)(g_ybuf + (size_t)s1 * D_IN + dd);
    float4 r = make_float4(a.x + b.x, a.y + b.y, a.z + b.z, a.w + b.w);
    *(float4*)(out + (size_t)t * D_IN + dd) = r;
}

extern "C" void kernel_launch(void* const* d_in, const int* in_sizes, int n_in,
                              void* d_out, int out_size) {
    const float* x  = (const float*)d_in[0];
    const float* Wg = (const float*)d_in[1];
    const float* bg = (const float*)d_in[2];
    const float* W1 = (const float*)d_in[3];
    const float* b1 = (const float*)d_in[4];
    const float* W2 = (const float*)d_in[5];
    const float* b2 = (const float*)d_in[6];
    float* out = (float*)d_out;

    float* gates_out = nullptr;
    if (out_size >= N_TOK * D_IN + N_TOK * E_EXP)
        gates_out = out + (size_t)N_TOK * D_IN;

    cudaFuncSetAttribute(mma_gemm_kernel<D_IN, H_DIM, true, true, false>,
                         cudaFuncAttributeMaxDynamicSharedMemorySize, SMEM_BYTES);
    cudaFuncSetAttribute(mma_gemm_kernel<H_DIM, D_IN, false, false, true>,
                         cudaFuncAttributeMaxDynamicSharedMemorySize, SMEM_BYTES);

    __half *xhi, *xlo, *w1h, *w2h, *hhi, *hlo;
    cudaGetSymbolAddress((void**)&xhi, gx_hi);
    cudaGetSymbolAddress((void**)&xlo, gx_lo);
    cudaGetSymbolAddress((void**)&w1h, gW1t_hi);
    cudaGetSymbolAddress((void**)&w2h, gW2t_hi);
    cudaGetSymbolAddress((void**)&hhi, gh_hi);
    cudaGetSymbolAddress((void**)&hlo, gh_lo);

    // 1: fused W1+W2 transpose (hi only) + routing init
    split_wt_all_kernel<<<dim3(H_DIM / 32, H_DIM / 32, 2 * E_EXP), 256>>>(W1, W2);
    // 2: gate + x split
    gate_kernel<<<(N_TOK * 32 + 255) / 256, 256>>>(x, Wg, bg, gates_out);
    // 3: scatter
    scatter_kernel<<<(N_TOK * TOPK + 255) / 256, 256>>>();
    // 4: GEMM1 (profiled slot)
    dim3 g1(H_DIM / BN, SLOTS / BM);   // (16, 136)
    mma_gemm_kernel<D_IN, H_DIM, true, true, false>
        <<<g1, 256, SMEM_BYTES>>>(xhi, xlo, w1h, b1);
    // 5: GEMM2
    dim3 g2(D_IN / BN, SLOTS / BM);    // (4, 136)
    mma_gemm_kernel<H_DIM, D_IN, false, false, true>
        <<<g2, 256, SMEM_BYTES>>>(hhi, hlo, w2h, b2);
    // 6: combine
    combine_kernel<<<(N_TOK * (D_IN / 4) + 255) / 256, 256>>>(out);
}

// round 14
// speedup vs baseline: 2.2405x; 1.6517x over previous
#include <cuda_runtime.h>
#include <cuda_fp16.h>
#include <math.h>
#include <stdint.h>

#define N_TOK 4096
#define D_IN  512
#define E_EXP 8
#define TOPK  2
#define H_DIM 2048

#define BM 64
#define BN 128
#define BK 32
#define SLOTS (N_TOK*TOPK + E_EXP*BM)   // 8704 padded slots

// smem: Ah[64x32] Bh[128x32] fp16, 64B rows, XOR-swizzled
#define OAH 0
#define OBH 4096
#define STAGE_BYTES 12288
#define NSTAGE 4
#define SMEM_BYTES (NSTAGE * STAGE_BYTES)   // 49152

// -------- scratch (device globals; no allocation allowed) --------
__device__ int   g_counts[E_EXP];
__device__ int   g_cnt2[E_EXP];
__device__ int   g_off[E_EXP + 1];
__device__ int   g_slot_tok[SLOTS];
__device__ float g_slot_w[SLOTS];
__device__ int   g_tok_slot[N_TOK * TOPK];
__device__ float g_topw[N_TOK * TOPK];
__device__ int   g_topi[N_TOK * TOPK];

__device__ __half gx_hi[(size_t)N_TOK * D_IN];
__device__ __half gW1t_hi[(size_t)E_EXP * H_DIM * D_IN]; // [e][n][k]
__device__ __half gW2t_hi[(size_t)E_EXP * D_IN * H_DIM]; // [e][n][k]
__device__ __half gh_hi[(size_t)SLOTS * H_DIM];
__device__ float g_ybuf[(size_t)SLOTS * D_IN];

// -------- helpers --------
__device__ __forceinline__ void cp16(uint32_t dst, const void* src, int srcBytes) {
    asm volatile("cp.async.cg.shared.global [%0], [%1], 16, %2;"
                 :: "r"(dst), "l"(src), "r"(srcBytes) : "memory");
}
__device__ __forceinline__ void cp_commit() {
    asm volatile("cp.async.commit_group;" ::: "memory");
}
template<int N> __device__ __forceinline__ void cp_wait() {
    asm volatile("cp.async.wait_group %0;" :: "n"(N) : "memory");
}
__device__ __forceinline__ void ldsm4(uint32_t* r, uint32_t addr) {
    asm volatile("ldmatrix.sync.aligned.m8n8.x4.shared.b16 {%0,%1,%2,%3}, [%4];"
                 : "=r"(r[0]), "=r"(r[1]), "=r"(r[2]), "=r"(r[3]) : "r"(addr));
}
__device__ __forceinline__ void mma_f16(float d[4],
                                        uint32_t a0, uint32_t a1, uint32_t a2, uint32_t a3,
                                        uint32_t b0, uint32_t b1) {
    asm volatile(
        "mma.sync.aligned.m16n8k16.row.col.f32.f16.f16.f32 "
        "{%0,%1,%2,%3},{%4,%5,%6,%7},{%8,%9},{%0,%1,%2,%3};"
        : "+f"(d[0]), "+f"(d[1]), "+f"(d[2]), "+f"(d[3])
        : "r"(a0), "r"(a1), "r"(a2), "r"(a3), "r"(b0), "r"(b1));
}
// swizzled byte offset of 16B chunk c (0..3) in 64B row r
__device__ __forceinline__ uint32_t swz(int r, int c) {
    return (uint32_t)(r * 64 + ((c ^ ((r >> 1) & 3)) * 16));
}
__device__ __forceinline__ uint32_t pack2h(float a, float b) {
    __half2 h = __halves2half2(__float2half(a), __float2half(b));
    return *(uint32_t*)&h;
}

// -------- 1: fused W1+W2 transpose (fp16) + routing-state init --------
__global__ void split_wt_all_kernel(const float* __restrict__ W1,
                                    const float* __restrict__ W2) {
    if (blockIdx.z == 0 && blockIdx.y == 0) {
        int idx = blockIdx.x * blockDim.x + threadIdx.x;
        if (idx < SLOTS) g_slot_tok[idx] = -1;
        if (idx < E_EXP) { g_counts[idx] = 0; g_cnt2[idx] = 0; }
    }
    int z = blockIdx.z;
    const float* src; __half* dhi; int K, N, e;
    if (z < E_EXP) { e = z;         src = W1; dhi = gW1t_hi; K = D_IN;  N = H_DIM; }
    else           { e = z - E_EXP; src = W2; dhi = gW2t_hi; K = H_DIM; N = D_IN;  }
    int n0 = blockIdx.x * 32, k0 = blockIdx.y * 32;
    if (n0 >= N || k0 >= K) return;

    __shared__ float t[32][33];
    const float* s = src + (size_t)e * K * N;
    int tx = threadIdx.x & 31, ty = threadIdx.x >> 5;
#pragma unroll
    for (int i = 0; i < 4; i++)
        t[ty + 8 * i][tx] = s[(size_t)(k0 + ty + 8 * i) * N + n0 + tx];
    __syncthreads();
    size_t ob = (size_t)e * K * N;
#pragma unroll
    for (int i = 0; i < 4; i++) {
        int n = n0 + ty + 8 * i, k = k0 + tx;
        dhi[ob + (size_t)n * K + k] = __float2half(t[tx][ty + 8 * i]);
    }
}

// -------- 2: gating + x fp16 convert (one warp per token) --------
__global__ void gate_kernel(const float* __restrict__ x,
                            const float* __restrict__ Wg,
                            const float* __restrict__ bg,
                            float* __restrict__ gates_out) {
    int t    = (blockIdx.x * blockDim.x + threadIdx.x) >> 5;
    int lane = threadIdx.x & 31;
    if (t >= N_TOK) return;
    const float* xr = x + (size_t)t * D_IN;

    float acc[E_EXP];
#pragma unroll
    for (int e = 0; e < E_EXP; e++) acc[e] = 0.f;
#pragma unroll
    for (int i = 0; i < 4; i++) {
        int d0 = i * 128 + lane * 4;
        float4 xv = *(const float4*)(xr + d0);
        uint32_t h0 = pack2h(xv.x, xv.y), h1 = pack2h(xv.z, xv.w);
        size_t o = (size_t)t * D_IN + d0;
        *(uint2*)(gx_hi + o) = make_uint2(h0, h1);
        float xs[4] = {xv.x, xv.y, xv.z, xv.w};
#pragma unroll
        for (int j = 0; j < 4; j++) {
            const float4* wr = (const float4*)(Wg + (d0 + j) * E_EXP);
            float4 w0 = wr[0], w1 = wr[1];
            acc[0] = fmaf(xs[j], w0.x, acc[0]); acc[1] = fmaf(xs[j], w0.y, acc[1]);
            acc[2] = fmaf(xs[j], w0.z, acc[2]); acc[3] = fmaf(xs[j], w0.w, acc[3]);
            acc[4] = fmaf(xs[j], w1.x, acc[4]); acc[5] = fmaf(xs[j], w1.y, acc[5]);
            acc[6] = fmaf(xs[j], w1.z, acc[6]); acc[7] = fmaf(xs[j], w1.w, acc[7]);
        }
    }
#pragma unroll
    for (int o = 16; o > 0; o >>= 1) {
#pragma unroll
        for (int e = 0; e < E_EXP; e++)
            acc[e] += __shfl_xor_sync(0xffffffffu, acc[e], o);
    }
    if (lane == 0) {
        float l[E_EXP], p[E_EXP];
        float m = -1e30f;
#pragma unroll
        for (int e = 0; e < E_EXP; e++) { l[e] = acc[e] + bg[e]; m = fmaxf(m, l[e]); }
        float s = 0.f;
#pragma unroll
        for (int e = 0; e < E_EXP; e++) { p[e] = __expf(l[e] - m); s += p[e]; }
        float inv = 1.f / s;
#pragma unroll
        for (int e = 0; e < E_EXP; e++) p[e] *= inv;
        if (gates_out) {
#pragma unroll
            for (int e = 0; e < E_EXP; e++) gates_out[t * E_EXP + e] = p[e];
        }
        int i1 = 0; float p1 = p[0];
#pragma unroll
        for (int e = 1; e < E_EXP; e++) if (p[e] > p1) { p1 = p[e]; i1 = e; }
        int i2 = -1; float p2 = -1.f;
#pragma unroll
        for (int e = 0; e < E_EXP; e++) if (e != i1 && p[e] > p2) { p2 = p[e]; i2 = e; }
        g_topw[t * 2 + 0] = p1;  g_topi[t * 2 + 0] = i1;
        g_topw[t * 2 + 1] = p2;  g_topi[t * 2 + 1] = i2;
        atomicAdd(&g_counts[i1], 1);
        atomicAdd(&g_counts[i2], 1);
    }
}

// -------- 3: scatter (scan folded in; pads to BM=64) --------
__global__ void scatter_kernel() {
    __shared__ int soff[E_EXP + 1];
    if (threadIdx.x == 0) {
        int o = 0;
#pragma unroll
        for (int e = 0; e < E_EXP; e++) {
            soff[e] = o;
            o += ((g_counts[e] + BM - 1) / BM) * BM;
        }
        soff[E_EXP] = o;
        if (blockIdx.x == 0) {
#pragma unroll
            for (int e = 0; e <= E_EXP; e++) g_off[e] = soff[e];
        }
    }
    __syncthreads();
    int i = blockIdx.x * blockDim.x + threadIdx.x;
    if (i >= N_TOK * TOPK) return;
    int e = g_topi[i];
    int pos = soff[e] + atomicAdd(&g_cnt2[e], 1);
    g_slot_tok[pos] = i >> 1;
    g_slot_w[pos]   = g_topw[i];
    g_tok_slot[i]   = pos;
}

// -------- grouped single-pass fp16 GEMM: CTA 64x128, warp 32x32, 3 CTAs/SM --------
template<int KTOT, int NTOT, bool GATHER, bool RELU, bool SCALE>
__global__ void __launch_bounds__(256, 3)
mma_gemm_kernel(const __half* __restrict__ Ahi,
                const __half* __restrict__ Bthi,
                const float* __restrict__ Bias)
{
    constexpr int KT = KTOT / BK;
    extern __shared__ char smem[];
    __shared__ int   sTok[BM];
    __shared__ float sW[BM];

    const int m0 = blockIdx.y * BM;
    const int n0 = blockIdx.x * BN;
    if (m0 >= g_off[E_EXP]) return;
    int e = 0;
#pragma unroll
    for (int i = 1; i < E_EXP; i++) if (m0 >= g_off[i]) e = i;

    const int tid = threadIdx.x;
    if (tid < BM) {
        if (GATHER) sTok[tid] = g_slot_tok[m0 + tid];
        if (SCALE)  sW[tid]   = g_slot_w[m0 + tid];
    }
    __syncthreads();

    const __half* Wh = Bthi + (size_t)e * NTOT * KTOT;

    // staging: A rows tid>>2 (chunk tid&3), B rows tid>>1 (chunks 2*(tid&1)+{0,1})
    const int arowi = tid >> 2;
    const int ac    = tid & 3;
    const int browi = tid >> 1;
    const int bc    = (tid & 1) * 2;

    const __half* arow_h;
    int abytes = 16;
    if (GATHER) {
        int tok = sTok[arowi];
        if (tok >= 0) arow_h = Ahi + (size_t)tok * KTOT + ac * 8;
        else          { arow_h = Ahi; abytes = 0; }
    } else {
        arow_h = Ahi + (size_t)(m0 + arowi) * KTOT + ac * 8;
    }
    const __half* brow_h = Wh + (size_t)(n0 + browi) * KTOT + bc * 8;

    const uint32_t sbase = (uint32_t)__cvta_generic_to_shared(smem);
    const uint32_t da  = swz(arowi, ac);
    const uint32_t db0 = swz(browi, bc);
    const uint32_t db1 = swz(browi, bc + 1);

    auto stage = [&](int buf, int k0) {
        uint32_t sb = sbase + buf * STAGE_BYTES;
        cp16(sb + OAH + da,  arow_h + k0, abytes);
        cp16(sb + OBH + db0, brow_h + k0, 16);
        cp16(sb + OBH + db1, brow_h + k0 + 8, 16);
        cp_commit();
    };

    const int lane = tid & 31;
    const int wm = (tid >> 5) >> 2;  // 0..1 (32 rows each)
    const int wn = (tid >> 5) & 3;   // 0..3 (32 cols each)
    const int g  = lane >> 3;
    const int lr = lane & 7;

    const int arow0 = wm * 32 + lr + (g & 1) * 8;
    const uint32_t aswz = ((uint32_t)(arow0 >> 1) & 3);
    uint32_t aoff[2];
#pragma unroll
    for (int ks = 0; ks < 2; ks++)
        aoff[ks] = (uint32_t)(arow0 * 64) + (((uint32_t)(ks * 2 + (g >> 1)) ^ aswz) * 16);

    const int brow0 = wn * 32 + lr + ((g >> 1) & 1) * 8;
    const uint32_t bswz = ((uint32_t)(brow0 >> 1) & 3);
    uint32_t boff[2];
#pragma unroll
    for (int ks = 0; ks < 2; ks++)
        boff[ks] = (uint32_t)(brow0 * 64) + (((uint32_t)(ks * 2 + (g & 1)) ^ bswz) * 16);

    float acc[2][4][4];
#pragma unroll
    for (int mt = 0; mt < 2; mt++)
#pragma unroll
        for (int nt = 0; nt < 4; nt++)
#pragma unroll
            for (int i = 0; i < 4; i++) acc[mt][nt][i] = 0.f;

    stage(0, 0);
    stage(1, BK);
    stage(2, 2 * BK);
    int buf = 0;
    for (int kt = 0; kt < KT; kt++) {
        if (kt < KT - 2) cp_wait<2>();
        else if (kt < KT - 1) cp_wait<1>();
        else cp_wait<0>();
        __syncthreads();
        if (kt + 3 < KT) {
            int nb = buf + 3; if (nb >= NSTAGE) nb -= NSTAGE;
            stage(nb, (kt + 3) * BK);
        }
        const uint32_t sb = sbase + buf * STAGE_BYTES;
#pragma unroll
        for (int ks = 0; ks < 2; ks++) {
            uint32_t bh[8];
#pragma unroll
            for (int np = 0; np < 2; np++)
                ldsm4(&bh[np * 4], sb + OBH + boff[ks] + np * 1024);
            uint32_t ah[2][4];
#pragma unroll
            for (int mt = 0; mt < 2; mt++)
                ldsm4(ah[mt], sb + OAH + aoff[ks] + mt * 1024);
#pragma unroll
            for (int mt = 0; mt < 2; mt++)
#pragma unroll
                for (int nt = 0; nt < 4; nt++) {
                    int i0 = (nt >> 1) * 4 + (nt & 1) * 2;
                    mma_f16(acc[mt][nt], ah[mt][0], ah[mt][1], ah[mt][2], ah[mt][3],
                            bh[i0], bh[i0 + 1]);
                }
        }
        buf++; if (buf >= NSTAGE) buf = 0;
    }

    const int r = lane >> 2;
    const int c = lane & 3;
    const float* bias = Bias + (size_t)e * NTOT;
#pragma unroll
    for (int mt = 0; mt < 2; mt++) {
        int row0 = m0 + wm * 32 + mt * 16 + r;
        int lrow = wm * 32 + mt * 16 + r;
#pragma unroll
        for (int nt = 0; nt < 4; nt++) {
            int col = n0 + wn * 32 + nt * 8 + 2 * c;
            float b0v = bias[col], b1v = bias[col + 1];
            float v0 = acc[mt][nt][0] + b0v, v1 = acc[mt][nt][1] + b1v;
            float v2 = acc[mt][nt][2] + b0v, v3 = acc[mt][nt][3] + b1v;
            if (RELU) {
                v0 = fmaxf(v0, 0.f); v1 = fmaxf(v1, 0.f);
                v2 = fmaxf(v2, 0.f); v3 = fmaxf(v3, 0.f);
                size_t o0 = (size_t)row0 * NTOT + col;
                size_t o2 = o0 + (size_t)8 * NTOT;
                __half2 p01 = __halves2half2(__float2half(v0), __float2half(v1));
                __half2 p23 = __halves2half2(__float2half(v2), __float2half(v3));
                *(__half2*)&gh_hi[o0] = p01;
                *(__half2*)&gh_hi[o2] = p23;
            } else {
                float w0 = SCALE ? sW[lrow]     : 1.f;
                float w1 = SCALE ? sW[lrow + 8] : 1.f;
                float* o0 = g_ybuf + (size_t)row0 * NTOT + col;
                *(float2*)o0 = make_float2(v0 * w0, v1 * w0);
                *(float2*)(o0 + (size_t)8 * NTOT) = make_float2(v2 * w1, v3 * w1);
            }
        }
    }
}

// -------- 6: deterministic combine --------
__global__ void combine_kernel(float* __restrict__ out) {
    int i = blockIdx.x * blockDim.x + threadIdx.x;
    if (i >= N_TOK * (D_IN / 4)) return;
    int t  = i >> 7;
    int dd = (i & 127) << 2;
    int s0 = g_tok_slot[t * 2 + 0];
    int s1 = g_tok_slot[t * 2 + 1];
    float4 a = *(const float4*)(g_ybuf + (size_t)s0 * D_IN + dd);
    float4 b = *(const float4*)(g_ybuf + (size_t)s1 * D_IN + dd);
    float4 r = make_float4(a.x + b.x, a.y + b.y, a.z + b.z, a.w + b.w);
    *(float4*)(out + (size_t)t * D_IN + dd) = r;
}

extern "C" void kernel_launch(void* const* d_in, const int* in_sizes, int n_in,
                              void* d_out, int out_size) {
    const float* x  = (const float*)d_in[0];
    const float* Wg = (const float*)d_in[1];
    const float* bg = (const float*)d_in[2];
    const float* W1 = (const float*)d_in[3];
    const float* b1 = (const float*)d_in[4];
    const float* W2 = (const float*)d_in[5];
    const float* b2 = (const float*)d_in[6];
    float* out = (float*)d_out;

    float* gates_out = nullptr;
    if (out_size >= N_TOK * D_IN + N_TOK * E_EXP)
        gates_out = out + (size_t)N_TOK * D_IN;

    cudaFuncSetAttribute(mma_gemm_kernel<D_IN, H_DIM, true, true, false>,
                         cudaFuncAttributeMaxDynamicSharedMemorySize, SMEM_BYTES);
    cudaFuncSetAttribute(mma_gemm_kernel<H_DIM, D_IN, false, false, true>,
                         cudaFuncAttributeMaxDynamicSharedMemorySize, SMEM_BYTES);

    __half *xhi, *w1h, *w2h, *hhi;
    cudaGetSymbolAddress((void**)&xhi, gx_hi);
    cudaGetSymbolAddress((void**)&w1h, gW1t_hi);
    cudaGetSymbolAddress((void**)&w2h, gW2t_hi);
    cudaGetSymbolAddress((void**)&hhi, gh_hi);

    // 1: fused W1+W2 transpose + routing init
    split_wt_all_kernel<<<dim3(H_DIM / 32, H_DIM / 32, 2 * E_EXP), 256>>>(W1, W2);
    // 2: gate + x convert
    gate_kernel<<<(N_TOK * 32 + 255) / 256, 256>>>(x, Wg, bg, gates_out);
    // 3: scatter
    scatter_kernel<<<(N_TOK * TOPK + 255) / 256, 256>>>();
    // 4: GEMM1 (profiled slot)
    dim3 g1(H_DIM / BN, SLOTS / BM);   // (16, 136)
    mma_gemm_kernel<D_IN, H_DIM, true, true, false>
        <<<g1, 256, SMEM_BYTES>>>(xhi, w1h, b1);
    // 5: GEMM2
    dim3 g2(D_IN / BN, SLOTS / BM);    // (4, 136)
    mma_gemm_kernel<H_DIM, D_IN, false, false, true>
        <<<g2, 256, SMEM_BYTES>>>(hhi, w2h, b2);
    // 6: combine
    combine_kernel<<<(N_TOK * (D_IN / 4) + 255) / 256, 256>>>(out);
}

// round 15
// speedup vs baseline: 2.4567x; 1.0965x over previous
#include <cuda_runtime.h>
#include <cuda_fp16.h>
#include <math.h>
#include <stdint.h>

#define N_TOK 4096
#define D_IN  512
#define E_EXP 8
#define TOPK  2
#define H_DIM 2048

#define BM 64
#define BN 128
#define BK 32
#define SLOTS (N_TOK*TOPK + E_EXP*BM)   // 8704 padded slots

// smem: Ah[64x32] Bh[128x32] fp16, 64B rows, XOR-swizzled
#define OAH 0
#define OBH 4096
#define STAGE_BYTES 12288
#define NSTAGE 4
#define SMEM_BYTES (NSTAGE * STAGE_BYTES)   // 49152

// -------- scratch (device globals; no allocation allowed) --------
__device__ int   g_counts[E_EXP];
__device__ int   g_cnt2[E_EXP];
__device__ int   g_off[E_EXP + 1];
__device__ int   g_slot_tok[SLOTS];
__device__ float g_slot_w[SLOTS];
__device__ float g_topw[N_TOK * TOPK];
__device__ int   g_topi[N_TOK * TOPK];

__device__ __half gx_hi[(size_t)N_TOK * D_IN];
__device__ __half gW1t_hi[(size_t)E_EXP * H_DIM * D_IN]; // [e][n][k]
__device__ __half gW2t_hi[(size_t)E_EXP * D_IN * H_DIM]; // [e][n][k]
__device__ __half gh_hi[(size_t)SLOTS * H_DIM];

// -------- helpers --------
__device__ __forceinline__ void cp16(uint32_t dst, const void* src, int srcBytes) {
    asm volatile("cp.async.cg.shared.global [%0], [%1], 16, %2;"
                 :: "r"(dst), "l"(src), "r"(srcBytes) : "memory");
}
__device__ __forceinline__ void cp_commit() {
    asm volatile("cp.async.commit_group;" ::: "memory");
}
template<int N> __device__ __forceinline__ void cp_wait() {
    asm volatile("cp.async.wait_group %0;" :: "n"(N) : "memory");
}
__device__ __forceinline__ void ldsm4(uint32_t* r, uint32_t addr) {
    asm volatile("ldmatrix.sync.aligned.m8n8.x4.shared.b16 {%0,%1,%2,%3}, [%4];"
                 : "=r"(r[0]), "=r"(r[1]), "=r"(r[2]), "=r"(r[3]) : "r"(addr));
}
__device__ __forceinline__ void mma_f16(float d[4],
                                        uint32_t a0, uint32_t a1, uint32_t a2, uint32_t a3,
                                        uint32_t b0, uint32_t b1) {
    asm volatile(
        "mma.sync.aligned.m16n8k16.row.col.f32.f16.f16.f32 "
        "{%0,%1,%2,%3},{%4,%5,%6,%7},{%8,%9},{%0,%1,%2,%3};"
        : "+f"(d[0]), "+f"(d[1]), "+f"(d[2]), "+f"(d[3])
        : "r"(a0), "r"(a1), "r"(a2), "r"(a3), "r"(b0), "r"(b1));
}
// swizzled byte offset of 16B chunk c (0..3) in 64B row r
__device__ __forceinline__ uint32_t swz(int r, int c) {
    return (uint32_t)(r * 64 + ((c ^ ((r >> 1) & 3)) * 16));
}
__device__ __forceinline__ uint32_t pack2h(float a, float b) {
    __half2 h = __halves2half2(__float2half(a), __float2half(b));
    return *(uint32_t*)&h;
}

// -------- 1: fused W1+W2 transpose-convert (half2 writes) + routing init --------
// Tile: 32 n x 64 k. Reads coalesced along n; writes 128B/warp via __half2.
__global__ void split_wt_all_kernel(const float* __restrict__ W1,
                                    const float* __restrict__ W2) {
    if (blockIdx.z == 0 && blockIdx.y == 0) {
        int idx = blockIdx.x * blockDim.x + threadIdx.x;
        if (idx < SLOTS) g_slot_tok[idx] = -1;
        if (idx < E_EXP) { g_counts[idx] = 0; g_cnt2[idx] = 0; }
    }
    int z = blockIdx.z;
    const float* src; __half* dhi; int K, N, e;
    if (z < E_EXP) { e = z;         src = W1; dhi = gW1t_hi; K = D_IN;  N = H_DIM; }
    else           { e = z - E_EXP; src = W2; dhi = gW2t_hi; K = H_DIM; N = D_IN;  }
    int n0 = blockIdx.x * 32, k0 = blockIdx.y * 64;
    if (n0 >= N || k0 >= K) return;

    __shared__ float t[64][33];   // [k_local][n_local]
    const float* s = src + (size_t)e * K * N;
    int tx = threadIdx.x & 31, ty = threadIdx.x >> 5;
#pragma unroll
    for (int i = 0; i < 8; i++)
        t[ty + 8 * i][tx] = s[(size_t)(k0 + ty + 8 * i) * N + n0 + tx];
    __syncthreads();
    size_t ob = (size_t)e * K * N;
    int kl = tx * 2;
#pragma unroll
    for (int i = 0; i < 4; i++) {
        int nl = ty + 8 * i;
        __half2 v = __halves2half2(__float2half(t[kl][nl]), __float2half(t[kl + 1][nl]));
        *(__half2*)&dhi[ob + (size_t)(n0 + nl) * K + k0 + kl] = v;
    }
}

// -------- 2: gating + x fp16 convert + zero out-region (one warp per token) --------
__global__ void gate_kernel(const float* __restrict__ x,
                            const float* __restrict__ Wg,
                            const float* __restrict__ bg,
                            float* __restrict__ out,
                            float* __restrict__ gates_out) {
    int gtid = blockIdx.x * blockDim.x + threadIdx.x;
    // zero the accumulated out region (N_TOK*D_IN floats) — 4 float4 per thread
    {
        float4* o4 = (float4*)out;
#pragma unroll
        for (int i = 0; i < 4; i++) {
            int idx = gtid + i * (N_TOK * 32);   // grid has N_TOK*32 threads
            if (idx < N_TOK * D_IN / 4) o4[idx] = make_float4(0.f, 0.f, 0.f, 0.f);
        }
    }
    int t    = gtid >> 5;
    int lane = threadIdx.x & 31;
    if (t >= N_TOK) return;
    const float* xr = x + (size_t)t * D_IN;

    float acc[E_EXP];
#pragma unroll
    for (int e = 0; e < E_EXP; e++) acc[e] = 0.f;
#pragma unroll
    for (int i = 0; i < 4; i++) {
        int d0 = i * 128 + lane * 4;
        float4 xv = *(const float4*)(xr + d0);
        uint32_t h0 = pack2h(xv.x, xv.y), h1 = pack2h(xv.z, xv.w);
        size_t o = (size_t)t * D_IN + d0;
        *(uint2*)(gx_hi + o) = make_uint2(h0, h1);
        float xs[4] = {xv.x, xv.y, xv.z, xv.w};
#pragma unroll
        for (int j = 0; j < 4; j++) {
            const float4* wr = (const float4*)(Wg + (d0 + j) * E_EXP);
            float4 w0 = wr[0], w1 = wr[1];
            acc[0] = fmaf(xs[j], w0.x, acc[0]); acc[1] = fmaf(xs[j], w0.y, acc[1]);
            acc[2] = fmaf(xs[j], w0.z, acc[2]); acc[3] = fmaf(xs[j], w0.w, acc[3]);
            acc[4] = fmaf(xs[j], w1.x, acc[4]); acc[5] = fmaf(xs[j], w1.y, acc[5]);
            acc[6] = fmaf(xs[j], w1.z, acc[6]); acc[7] = fmaf(xs[j], w1.w, acc[7]);
        }
    }
#pragma unroll
    for (int o = 16; o > 0; o >>= 1) {
#pragma unroll
        for (int e = 0; e < E_EXP; e++)
            acc[e] += __shfl_xor_sync(0xffffffffu, acc[e], o);
    }
    if (lane == 0) {
        float l[E_EXP], p[E_EXP];
        float m = -1e30f;
#pragma unroll
        for (int e = 0; e < E_EXP; e++) { l[e] = acc[e] + bg[e]; m = fmaxf(m, l[e]); }
        float s = 0.f;
#pragma unroll
        for (int e = 0; e < E_EXP; e++) { p[e] = __expf(l[e] - m); s += p[e]; }
        float inv = 1.f / s;
#pragma unroll
        for (int e = 0; e < E_EXP; e++) p[e] *= inv;
        if (gates_out) {
#pragma unroll
            for (int e = 0; e < E_EXP; e++) gates_out[t * E_EXP + e] = p[e];
        }
        int i1 = 0; float p1 = p[0];
#pragma unroll
        for (int e = 1; e < E_EXP; e++) if (p[e] > p1) { p1 = p[e]; i1 = e; }
        int i2 = -1; float p2 = -1.f;
#pragma unroll
        for (int e = 0; e < E_EXP; e++) if (e != i1 && p[e] > p2) { p2 = p[e]; i2 = e; }
        g_topw[t * 2 + 0] = p1;  g_topi[t * 2 + 0] = i1;
        g_topw[t * 2 + 1] = p2;  g_topi[t * 2 + 1] = i2;
        atomicAdd(&g_counts[i1], 1);
        atomicAdd(&g_counts[i2], 1);
    }
}

// -------- 3: scatter (scan folded in; pads to BM=64) --------
__global__ void scatter_kernel() {
    __shared__ int soff[E_EXP + 1];
    if (threadIdx.x == 0) {
        int o = 0;
#pragma unroll
        for (int e = 0; e < E_EXP; e++) {
            soff[e] = o;
            o += ((g_counts[e] + BM - 1) / BM) * BM;
        }
        soff[E_EXP] = o;
        if (blockIdx.x == 0) {
#pragma unroll
            for (int e = 0; e <= E_EXP; e++) g_off[e] = soff[e];
        }
    }
    __syncthreads();
    int i = blockIdx.x * blockDim.x + threadIdx.x;
    if (i >= N_TOK * TOPK) return;
    int e = g_topi[i];
    int pos = soff[e] + atomicAdd(&g_cnt2[e], 1);
    g_slot_tok[pos] = i >> 1;
    g_slot_w[pos]   = g_topw[i];
}

// -------- grouped single-pass fp16 GEMM --------
// RELU=true  (gemm1): hidden = relu(acc+b1) -> gh_hi (fp16)
// RELU=false (gemm2): atomicAdd(out[tok], (acc+b2)*w)  — 2 contributions/elem, commutative => deterministic
template<int KTOT, int NTOT, bool GATHER, bool RELU>
__global__ void __launch_bounds__(256, 3)
mma_gemm_kernel(const __half* __restrict__ Ahi,
                const __half* __restrict__ Bthi,
                const float* __restrict__ Bias,
                float* __restrict__ out)
{
    constexpr int KT = KTOT / BK;
    extern __shared__ char smem[];
    __shared__ int   sTok[BM];
    __shared__ float sW[BM];

    const int m0 = blockIdx.y * BM;
    const int n0 = blockIdx.x * BN;
    if (m0 >= g_off[E_EXP]) return;
    int e = 0;
#pragma unroll
    for (int i = 1; i < E_EXP; i++) if (m0 >= g_off[i]) e = i;

    const int tid = threadIdx.x;
    if (tid < BM) {
        sTok[tid] = g_slot_tok[m0 + tid];
        if (!RELU) sW[tid] = g_slot_w[m0 + tid];
    }
    __syncthreads();

    const __half* Wh = Bthi + (size_t)e * NTOT * KTOT;

    const int arowi = tid >> 2;
    const int ac    = tid & 3;
    const int browi = tid >> 1;
    const int bc    = (tid & 1) * 2;

    const __half* arow_h;
    int abytes = 16;
    if (GATHER) {
        int tok = sTok[arowi];
        if (tok >= 0) arow_h = Ahi + (size_t)tok * KTOT + ac * 8;
        else          { arow_h = Ahi; abytes = 0; }
    } else {
        arow_h = Ahi + (size_t)(m0 + arowi) * KTOT + ac * 8;
    }
    const __half* brow_h = Wh + (size_t)(n0 + browi) * KTOT + bc * 8;

    const uint32_t sbase = (uint32_t)__cvta_generic_to_shared(smem);
    const uint32_t da  = swz(arowi, ac);
    const uint32_t db0 = swz(browi, bc);
    const uint32_t db1 = swz(browi, bc + 1);

    auto stage = [&](int buf, int k0) {
        uint32_t sb = sbase + buf * STAGE_BYTES;
        cp16(sb + OAH + da,  arow_h + k0, abytes);
        cp16(sb + OBH + db0, brow_h + k0, 16);
        cp16(sb + OBH + db1, brow_h + k0 + 8, 16);
        cp_commit();
    };

    const int lane = tid & 31;
    const int wm = (tid >> 5) >> 2;  // 0..1
    const int wn = (tid >> 5) & 3;   // 0..3
    const int g  = lane >> 3;
    const int lr = lane & 7;

    const int arow0 = wm * 32 + lr + (g & 1) * 8;
    const uint32_t aswz = ((uint32_t)(arow0 >> 1) & 3);
    uint32_t aoff[2];
#pragma unroll
    for (int ks = 0; ks < 2; ks++)
        aoff[ks] = (uint32_t)(arow0 * 64) + (((uint32_t)(ks * 2 + (g >> 1)) ^ aswz) * 16);

    const int brow0 = wn * 32 + lr + ((g >> 1) & 1) * 8;
    const uint32_t bswz = ((uint32_t)(brow0 >> 1) & 3);
    uint32_t boff[2];
#pragma unroll
    for (int ks = 0; ks < 2; ks++)
        boff[ks] = (uint32_t)(brow0 * 64) + (((uint32_t)(ks * 2 + (g & 1)) ^ bswz) * 16);

    float acc[2][4][4];
#pragma unroll
    for (int mt = 0; mt < 2; mt++)
#pragma unroll
        for (int nt = 0; nt < 4; nt++)
#pragma unroll
            for (int i = 0; i < 4; i++) acc[mt][nt][i] = 0.f;

    stage(0, 0);
    stage(1, BK);
    stage(2, 2 * BK);
    int buf = 0;
    for (int kt = 0; kt < KT; kt++) {
        if (kt < KT - 2) cp_wait<2>();
        else if (kt < KT - 1) cp_wait<1>();
        else cp_wait<0>();
        __syncthreads();
        if (kt + 3 < KT) {
            int nb = buf + 3; if (nb >= NSTAGE) nb -= NSTAGE;
            stage(nb, (kt + 3) * BK);
        }
        const uint32_t sb = sbase + buf * STAGE_BYTES;
#pragma unroll
        for (int ks = 0; ks < 2; ks++) {
            uint32_t bh[8];
#pragma unroll
            for (int np = 0; np < 2; np++)
                ldsm4(&bh[np * 4], sb + OBH + boff[ks] + np * 1024);
            uint32_t ah[2][4];
#pragma unroll
            for (int mt = 0; mt < 2; mt++)
                ldsm4(ah[mt], sb + OAH + aoff[ks] + mt * 1024);
#pragma unroll
            for (int mt = 0; mt < 2; mt++)
#pragma unroll
                for (int nt = 0; nt < 4; nt++) {
                    int i0 = (nt >> 1) * 4 + (nt & 1) * 2;
                    mma_f16(acc[mt][nt], ah[mt][0], ah[mt][1], ah[mt][2], ah[mt][3],
                            bh[i0], bh[i0 + 1]);
                }
        }
        buf++; if (buf >= NSTAGE) buf = 0;
    }

    const int r = lane >> 2;
    const int c = lane & 3;
    const float* bias = Bias + (size_t)e * NTOT;
#pragma unroll
    for (int mt = 0; mt < 2; mt++) {
        int row0 = m0 + wm * 32 + mt * 16 + r;
        int lrow = wm * 32 + mt * 16 + r;
#pragma unroll
        for (int nt = 0; nt < 4; nt++) {
            int col = n0 + wn * 32 + nt * 8 + 2 * c;
            float b0v = bias[col], b1v = bias[col + 1];
            float v0 = acc[mt][nt][0] + b0v, v1 = acc[mt][nt][1] + b1v;
            float v2 = acc[mt][nt][2] + b0v, v3 = acc[mt][nt][3] + b1v;
            if (RELU) {
                v0 = fmaxf(v0, 0.f); v1 = fmaxf(v1, 0.f);
                v2 = fmaxf(v2, 0.f); v3 = fmaxf(v3, 0.f);
                size_t o0 = (size_t)row0 * NTOT + col;
                size_t o2 = o0 + (size_t)8 * NTOT;
                *(__half2*)&gh_hi[o0] = __halves2half2(__float2half(v0), __float2half(v1));
                *(__half2*)&gh_hi[o2] = __halves2half2(__float2half(v2), __float2half(v3));
            } else {
                int t0 = sTok[lrow], t1 = sTok[lrow + 8];
                float w0 = sW[lrow], w1 = sW[lrow + 8];
                if (t0 >= 0) {
                    float* o = out + (size_t)t0 * NTOT + col;
                    atomicAdd(o,     v0 * w0);
                    atomicAdd(o + 1, v1 * w0);
                }
                if (t1 >= 0) {
                    float* o = out + (size_t)t1 * NTOT + col;
                    atomicAdd(o,     v2 * w1);
                    atomicAdd(o + 1, v3 * w1);
                }
            }
        }
    }
}

extern "C" void kernel_launch(void* const* d_in, const int* in_sizes, int n_in,
                              void* d_out, int out_size) {
    const float* x  = (const float*)d_in[0];
    const float* Wg = (const float*)d_in[1];
    const float* bg = (const float*)d_in[2];
    const float* W1 = (const float*)d_in[3];
    const float* b1 = (const float*)d_in[4];
    const float* W2 = (const float*)d_in[5];
    const float* b2 = (const float*)d_in[6];
    float* out = (float*)d_out;

    float* gates_out = nullptr;
    if (out_size >= N_TOK * D_IN + N_TOK * E_EXP)
        gates_out = out + (size_t)N_TOK * D_IN;

    cudaFuncSetAttribute(mma_gemm_kernel<D_IN, H_DIM, true, true>,
                         cudaFuncAttributeMaxDynamicSharedMemorySize, SMEM_BYTES);
    cudaFuncSetAttribute(mma_gemm_kernel<H_DIM, D_IN, false, false>,
                         cudaFuncAttributeMaxDynamicSharedMemorySize, SMEM_BYTES);

    __half *xhi, *w1h, *w2h, *hhi;
    cudaGetSymbolAddress((void**)&xhi, gx_hi);
    cudaGetSymbolAddress((void**)&w1h, gW1t_hi);
    cudaGetSymbolAddress((void**)&w2h, gW2t_hi);
    cudaGetSymbolAddress((void**)&hhi, gh_hi);

    // 1: fused W1+W2 transpose-convert + routing init
    //    grid covers max dims; per-z bounds checked in-kernel
    split_wt_all_kernel<<<dim3(H_DIM / 32, H_DIM / 64, 2 * E_EXP), 256>>>(W1, W2);
    // 2: gate + x convert + zero out region
    gate_kernel<<<(N_TOK * 32 + 255) / 256, 256>>>(x, Wg, bg, out, gates_out);
    // 3: scatter
    scatter_kernel<<<(N_TOK * TOPK + 255) / 256, 256>>>();
    // 4: GEMM1 (profiled slot)
    dim3 g1(H_DIM / BN, SLOTS / BM);   // (16, 136)
    mma_gemm_kernel<D_IN, H_DIM, true, true>
        <<<g1, 256, SMEM_BYTES>>>(xhi, w1h, b1, nullptr);
    // 5: GEMM2 + fused combine (deterministic 2-way atomics)
    dim3 g2(D_IN / BN, SLOTS / BM);    // (4, 136)
    mma_gemm_kernel<H_DIM, D_IN, false, false>
        <<<g2, 256, SMEM_BYTES>>>(hhi, w2h, b2, out);
}

// round 16
// speedup vs baseline: 2.4843x; 1.0112x over previous
#include <cuda_runtime.h>
#include <cuda_fp16.h>
#include <math.h>
#include <stdint.h>

#define N_TOK 4096
#define D_IN  512
#define E_EXP 8
#define TOPK  2
#define H_DIM 2048

#define BM 64
#define BN 128
#define BK 32
#define SLOTS (N_TOK*TOPK + E_EXP*BM)   // 8704 padded slots

// smem: Ah[64x32] Bh[128x32] fp16, 64B rows, XOR-swizzled
#define OAH 0
#define OBH 4096
#define STAGE_BYTES 12288
#define NSTAGE 4
#define SMEM_BYTES (NSTAGE * STAGE_BYTES)   // 49152

// -------- scratch (device globals; no allocation allowed) --------
__device__ int   g_counts[E_EXP];
__device__ int   g_cnt2[E_EXP];
__device__ int   g_off[E_EXP + 1];
__device__ int   g_slot_tok[SLOTS];
__device__ float g_slot_w[SLOTS];
__device__ float g_topw[N_TOK * TOPK];
__device__ int   g_topi[N_TOK * TOPK];

__device__ __half gx_hi[(size_t)N_TOK * D_IN];
__device__ __half gW1t_hi[(size_t)E_EXP * H_DIM * D_IN]; // [e][n][k]
__device__ __half gW2t_hi[(size_t)E_EXP * D_IN * H_DIM]; // [e][n][k]
__device__ __half gh_hi[(size_t)SLOTS * H_DIM];

// -------- helpers --------
__device__ __forceinline__ void cp16(uint32_t dst, const void* src, int srcBytes) {
    asm volatile("cp.async.cg.shared.global [%0], [%1], 16, %2;"
                 :: "r"(dst), "l"(src), "r"(srcBytes) : "memory");
}
__device__ __forceinline__ void cp_commit() {
    asm volatile("cp.async.commit_group;" ::: "memory");
}
template<int N> __device__ __forceinline__ void cp_wait() {
    asm volatile("cp.async.wait_group %0;" :: "n"(N) : "memory");
}
__device__ __forceinline__ void ldsm4(uint32_t* r, uint32_t addr) {
    asm volatile("ldmatrix.sync.aligned.m8n8.x4.shared.b16 {%0,%1,%2,%3}, [%4];"
                 : "=r"(r[0]), "=r"(r[1]), "=r"(r[2]), "=r"(r[3]) : "r"(addr));
}
__device__ __forceinline__ void mma_f16(float d[4],
                                        uint32_t a0, uint32_t a1, uint32_t a2, uint32_t a3,
                                        uint32_t b0, uint32_t b1) {
    asm volatile(
        "mma.sync.aligned.m16n8k16.row.col.f32.f16.f16.f32 "
        "{%0,%1,%2,%3},{%4,%5,%6,%7},{%8,%9},{%0,%1,%2,%3};"
        : "+f"(d[0]), "+f"(d[1]), "+f"(d[2]), "+f"(d[3])
        : "r"(a0), "r"(a1), "r"(a2), "r"(a3), "r"(b0), "r"(b1));
}
// swizzled byte offset of 16B chunk c (0..3) in 64B row r
__device__ __forceinline__ uint32_t swz(int r, int c) {
    return (uint32_t)(r * 64 + ((c ^ ((r >> 1) & 3)) * 16));
}
__device__ __forceinline__ uint32_t pack2h(float a, float b) {
    __half2 h = __halves2half2(__float2half(a), __float2half(b));
    return *(uint32_t*)&h;
}

// -------- 1: fused W1+W2 transpose-convert (half2 writes) + routing init --------
__global__ void split_wt_all_kernel(const float* __restrict__ W1,
                                    const float* __restrict__ W2) {
    if (blockIdx.z == 0 && blockIdx.y == 0) {
        int idx = blockIdx.x * blockDim.x + threadIdx.x;
        if (idx < SLOTS) g_slot_tok[idx] = -1;
        if (idx < E_EXP) { g_counts[idx] = 0; g_cnt2[idx] = 0; }
    }
    int z = blockIdx.z;
    const float* src; __half* dhi; int K, N, e;
    if (z < E_EXP) { e = z;         src = W1; dhi = gW1t_hi; K = D_IN;  N = H_DIM; }
    else           { e = z - E_EXP; src = W2; dhi = gW2t_hi; K = H_DIM; N = D_IN;  }
    int n0 = blockIdx.x * 32, k0 = blockIdx.y * 64;
    if (n0 >= N || k0 >= K) return;

    __shared__ float t[64][33];   // [k_local][n_local]
    const float* s = src + (size_t)e * K * N;
    int tx = threadIdx.x & 31, ty = threadIdx.x >> 5;
#pragma unroll
    for (int i = 0; i < 8; i++)
        t[ty + 8 * i][tx] = s[(size_t)(k0 + ty + 8 * i) * N + n0 + tx];
    __syncthreads();
    size_t ob = (size_t)e * K * N;
    int kl = tx * 2;
#pragma unroll
    for (int i = 0; i < 4; i++) {
        int nl = ty + 8 * i;
        __half2 v = __halves2half2(__float2half(t[kl][nl]), __float2half(t[kl + 1][nl]));
        *(__half2*)&dhi[ob + (size_t)(n0 + nl) * K + k0 + kl] = v;
    }
}

// -------- 2: gating (smem WgT) + x fp16 convert + zero out-region --------
__global__ void gate_kernel(const float* __restrict__ x,
                            const float* __restrict__ Wg,
                            const float* __restrict__ bg,
                            float* __restrict__ out,
                            float* __restrict__ gates_out) {
    __shared__ float sWgT[E_EXP * D_IN];   // [e][d], 16 KB
    int tid = threadIdx.x;
    for (int i = tid; i < D_IN * E_EXP; i += 256) {
        int d = i >> 3, e = i & 7;
        sWgT[e * D_IN + d] = Wg[i];
    }
    __syncthreads();

    int gtid = blockIdx.x * blockDim.x + threadIdx.x;
    // zero the accumulated out region (N_TOK*D_IN floats)
    {
        float4* o4 = (float4*)out;
#pragma unroll
        for (int i = 0; i < 4; i++) {
            int idx = gtid + i * (N_TOK * 32);
            if (idx < N_TOK * D_IN / 4) o4[idx] = make_float4(0.f, 0.f, 0.f, 0.f);
        }
    }
    int t    = gtid >> 5;
    int lane = threadIdx.x & 31;
    if (t >= N_TOK) return;
    const float* xr = x + (size_t)t * D_IN;

    float acc[E_EXP];
#pragma unroll
    for (int e = 0; e < E_EXP; e++) acc[e] = 0.f;
#pragma unroll
    for (int i = 0; i < 4; i++) {
        int d0 = i * 128 + lane * 4;
        float4 xv = *(const float4*)(xr + d0);
        uint32_t h0 = pack2h(xv.x, xv.y), h1 = pack2h(xv.z, xv.w);
        size_t o = (size_t)t * D_IN + d0;
        *(uint2*)(gx_hi + o) = make_uint2(h0, h1);
#pragma unroll
        for (int e = 0; e < E_EXP; e++) {
            float4 w = *(const float4*)&sWgT[e * D_IN + d0];
            acc[e] = fmaf(xv.x, w.x, acc[e]);
            acc[e] = fmaf(xv.y, w.y, acc[e]);
            acc[e] = fmaf(xv.z, w.z, acc[e]);
            acc[e] = fmaf(xv.w, w.w, acc[e]);
        }
    }
#pragma unroll
    for (int o = 16; o > 0; o >>= 1) {
#pragma unroll
        for (int e = 0; e < E_EXP; e++)
            acc[e] += __shfl_xor_sync(0xffffffffu, acc[e], o);
    }
    if (lane == 0) {
        float l[E_EXP], p[E_EXP];
        float m = -1e30f;
#pragma unroll
        for (int e = 0; e < E_EXP; e++) { l[e] = acc[e] + bg[e]; m = fmaxf(m, l[e]); }
        float s = 0.f;
#pragma unroll
        for (int e = 0; e < E_EXP; e++) { p[e] = __expf(l[e] - m); s += p[e]; }
        float inv = 1.f / s;
#pragma unroll
        for (int e = 0; e < E_EXP; e++) p[e] *= inv;
        if (gates_out) {
#pragma unroll
            for (int e = 0; e < E_EXP; e++) gates_out[t * E_EXP + e] = p[e];
        }
        int i1 = 0; float p1 = p[0];
#pragma unroll
        for (int e = 1; e < E_EXP; e++) if (p[e] > p1) { p1 = p[e]; i1 = e; }
        int i2 = -1; float p2 = -1.f;
#pragma unroll
        for (int e = 0; e < E_EXP; e++) if (e != i1 && p[e] > p2) { p2 = p[e]; i2 = e; }
        g_topw[t * 2 + 0] = p1;  g_topi[t * 2 + 0] = i1;
        g_topw[t * 2 + 1] = p2;  g_topi[t * 2 + 1] = i2;
        atomicAdd(&g_counts[i1], 1);
        atomicAdd(&g_counts[i2], 1);
    }
}

// -------- 3: scatter (scan folded in; warp-aggregated atomics) --------
__global__ void scatter_kernel() {
    __shared__ int soff[E_EXP + 1];
    if (threadIdx.x == 0) {
        int o = 0;
#pragma unroll
        for (int e = 0; e < E_EXP; e++) {
            soff[e] = o;
            o += ((g_counts[e] + BM - 1) / BM) * BM;
        }
        soff[E_EXP] = o;
        if (blockIdx.x == 0) {
#pragma unroll
            for (int e = 0; e <= E_EXP; e++) g_off[e] = soff[e];
        }
    }
    __syncthreads();
    int i = blockIdx.x * blockDim.x + threadIdx.x;   // grid covers exactly N_TOK*TOPK
    int lane = threadIdx.x & 31;
    int e = g_topi[i];
    int pos = 0;
#pragma unroll
    for (int ee = 0; ee < E_EXP; ee++) {
        unsigned m = __ballot_sync(0xffffffffu, e == ee);
        if (e == ee) {
            int leader = __ffs(m) - 1;
            int rank = __popc(m & ((1u << lane) - 1));
            int base = 0;
            if (lane == leader) base = atomicAdd(&g_cnt2[ee], __popc(m));
            base = __shfl_sync(m, base, leader);
            pos = soff[ee] + base + rank;
        }
    }
    g_slot_tok[pos] = i >> 1;
    g_slot_w[pos]   = g_topw[i];
}

// -------- grouped single-pass fp16 GEMM --------
// RELU=true  (gemm1): hidden = relu(acc+b1) -> gh_hi (fp16)
// RELU=false (gemm2): atomicAdd(out[tok], (acc+b2)*w) — 2 contributions/elem, commutative => deterministic
template<int KTOT, int NTOT, bool GATHER, bool RELU>
__global__ void __launch_bounds__(256, 3)
mma_gemm_kernel(const __half* __restrict__ Ahi,
                const __half* __restrict__ Bthi,
                const float* __restrict__ Bias,
                float* __restrict__ out)
{
    constexpr int KT = KTOT / BK;
    extern __shared__ char smem[];
    __shared__ int   sTok[BM];
    __shared__ float sW[BM];

    const int m0 = blockIdx.y * BM;
    const int n0 = blockIdx.x * BN;
    if (m0 >= g_off[E_EXP]) return;
    int e = 0;
#pragma unroll
    for (int i = 1; i < E_EXP; i++) if (m0 >= g_off[i]) e = i;

    const int tid = threadIdx.x;
    if (tid < BM) {
        sTok[tid] = g_slot_tok[m0 + tid];
        if (!RELU) sW[tid] = g_slot_w[m0 + tid];
    }
    __syncthreads();

    const __half* Wh = Bthi + (size_t)e * NTOT * KTOT;

    const int arowi = tid >> 2;
    const int ac    = tid & 3;
    const int browi = tid >> 1;
    const int bc    = (tid & 1) * 2;

    const __half* arow_h;
    int abytes = 16;
    if (GATHER) {
        int tok = sTok[arowi];
        if (tok >= 0) arow_h = Ahi + (size_t)tok * KTOT + ac * 8;
        else          { arow_h = Ahi; abytes = 0; }
    } else {
        arow_h = Ahi + (size_t)(m0 + arowi) * KTOT + ac * 8;
    }
    const __half* brow_h = Wh + (size_t)(n0 + browi) * KTOT + bc * 8;

    const uint32_t sbase = (uint32_t)__cvta_generic_to_shared(smem);
    const uint32_t da  = swz(arowi, ac);
    const uint32_t db0 = swz(browi, bc);
    const uint32_t db1 = swz(browi, bc + 1);

    auto stage = [&](int buf, int k0) {
        uint32_t sb = sbase + buf * STAGE_BYTES;
        cp16(sb + OAH + da,  arow_h + k0, abytes);
        cp16(sb + OBH + db0, brow_h + k0, 16);
        cp16(sb + OBH + db1, brow_h + k0 + 8, 16);
        cp_commit();
    };

    const int lane = tid & 31;
    const int wm = (tid >> 5) >> 2;  // 0..1
    const int wn = (tid >> 5) & 3;   // 0..3
    const int g  = lane >> 3;
    const int lr = lane & 7;

    const int arow0 = wm * 32 + lr + (g & 1) * 8;
    const uint32_t aswz = ((uint32_t)(arow0 >> 1) & 3);
    uint32_t aoff[2];
#pragma unroll
    for (int ks = 0; ks < 2; ks++)
        aoff[ks] = (uint32_t)(arow0 * 64) + (((uint32_t)(ks * 2 + (g >> 1)) ^ aswz) * 16);

    const int brow0 = wn * 32 + lr + ((g >> 1) & 1) * 8;
    const uint32_t bswz = ((uint32_t)(brow0 >> 1) & 3);
    uint32_t boff[2];
#pragma unroll
    for (int ks = 0; ks < 2; ks++)
        boff[ks] = (uint32_t)(brow0 * 64) + (((uint32_t)(ks * 2 + (g & 1)) ^ bswz) * 16);

    float acc[2][4][4];
#pragma unroll
    for (int mt = 0; mt < 2; mt++)
#pragma unroll
        for (int nt = 0; nt < 4; nt++)
#pragma unroll
            for (int i = 0; i < 4; i++) acc[mt][nt][i] = 0.f;

    stage(0, 0);
    stage(1, BK);
    stage(2, 2 * BK);
    int buf = 0;
    for (int kt = 0; kt < KT; kt++) {
        if (kt < KT - 2) cp_wait<2>();
        else if (kt < KT - 1) cp_wait<1>();
        else cp_wait<0>();
        __syncthreads();
        if (kt + 3 < KT) {
            int nb = buf + 3; if (nb >= NSTAGE) nb -= NSTAGE;
            stage(nb, (kt + 3) * BK);
        }
        const uint32_t sb = sbase + buf * STAGE_BYTES;
#pragma unroll
        for (int ks = 0; ks < 2; ks++) {
            uint32_t bh[8];
#pragma unroll
            for (int np = 0; np < 2; np++)
                ldsm4(&bh[np * 4], sb + OBH + boff[ks] + np * 1024);
            uint32_t ah[2][4];
#pragma unroll
            for (int mt = 0; mt < 2; mt++)
                ldsm4(ah[mt], sb + OAH + aoff[ks] + mt * 1024);
#pragma unroll
            for (int mt = 0; mt < 2; mt++)
#pragma unroll
                for (int nt = 0; nt < 4; nt++) {
                    int i0 = (nt >> 1) * 4 + (nt & 1) * 2;
                    mma_f16(acc[mt][nt], ah[mt][0], ah[mt][1], ah[mt][2], ah[mt][3],
                            bh[i0], bh[i0 + 1]);
                }
        }
        buf++; if (buf >= NSTAGE) buf = 0;
    }

    const int r = lane >> 2;
    const int c = lane & 3;
    const float* bias = Bias + (size_t)e * NTOT;
#pragma unroll
    for (int mt = 0; mt < 2; mt++) {
        int row0 = m0 + wm * 32 + mt * 16 + r;
        int lrow = wm * 32 + mt * 16 + r;
#pragma unroll
        for (int nt = 0; nt < 4; nt++) {
            int col = n0 + wn * 32 + nt * 8 + 2 * c;
            float b0v = bias[col], b1v = bias[col + 1];
            float v0 = acc[mt][nt][0] + b0v, v1 = acc[mt][nt][1] + b1v;
            float v2 = acc[mt][nt][2] + b0v, v3 = acc[mt][nt][3] + b1v;
            if (RELU) {
                v0 = fmaxf(v0, 0.f); v1 = fmaxf(v1, 0.f);
                v2 = fmaxf(v2, 0.f); v3 = fmaxf(v3, 0.f);
                size_t o0 = (size_t)row0 * NTOT + col;
                size_t o2 = o0 + (size_t)8 * NTOT;
                *(__half2*)&gh_hi[o0] = __halves2half2(__float2half(v0), __float2half(v1));
                *(__half2*)&gh_hi[o2] = __halves2half2(__float2half(v2), __float2half(v3));
            } else {
                int t0 = sTok[lrow], t1 = sTok[lrow + 8];
                float w0 = sW[lrow], w1 = sW[lrow + 8];
                if (t0 >= 0) {
                    float* o = out + (size_t)t0 * NTOT + col;
                    atomicAdd(o,     v0 * w0);
                    atomicAdd(o + 1, v1 * w0);
                }
                if (t1 >= 0) {
                    float* o = out + (size_t)t1 * NTOT + col;
                    atomicAdd(o,     v2 * w1);
                    atomicAdd(o + 1, v3 * w1);
                }
            }
        }
    }
}

extern "C" void kernel_launch(void* const* d_in, const int* in_sizes, int n_in,
                              void* d_out, int out_size) {
    const float* x  = (const float*)d_in[0];
    const float* Wg = (const float*)d_in[1];
    const float* bg = (const float*)d_in[2];
    const float* W1 = (const float*)d_in[3];
    const float* b1 = (const float*)d_in[4];
    const float* W2 = (const float*)d_in[5];
    const float* b2 = (const float*)d_in[6];
    float* out = (float*)d_out;

    float* gates_out = nullptr;
    if (out_size >= N_TOK * D_IN + N_TOK * E_EXP)
        gates_out = out + (size_t)N_TOK * D_IN;

    cudaFuncSetAttribute(mma_gemm_kernel<D_IN, H_DIM, true, true>,
                         cudaFuncAttributeMaxDynamicSharedMemorySize, SMEM_BYTES);
    cudaFuncSetAttribute(mma_gemm_kernel<H_DIM, D_IN, false, false>,
                         cudaFuncAttributeMaxDynamicSharedMemorySize, SMEM_BYTES);

    __half *xhi, *w1h, *w2h, *hhi;
    cudaGetSymbolAddress((void**)&xhi, gx_hi);
    cudaGetSymbolAddress((void**)&w1h, gW1t_hi);
    cudaGetSymbolAddress((void**)&w2h, gW2t_hi);
    cudaGetSymbolAddress((void**)&hhi, gh_hi);

    // 1: fused W1+W2 transpose-convert + routing init
    split_wt_all_kernel<<<dim3(H_DIM / 32, H_DIM / 64, 2 * E_EXP), 256>>>(W1, W2);
    // 2: gate (smem WgT) + x convert + zero out region
    gate_kernel<<<(N_TOK * 32 + 255) / 256, 256>>>(x, Wg, bg, out, gates_out);
    // 3: scatter (warp-aggregated)
    scatter_kernel<<<(N_TOK * TOPK) / 256, 256>>>();
    // 4: GEMM1 (profiled slot)
    dim3 g1(H_DIM / BN, SLOTS / BM);   // (16, 136)
    mma_gemm_kernel<D_IN, H_DIM, true, true>
        <<<g1, 256, SMEM_BYTES>>>(xhi, w1h, b1, nullptr);
    // 5: GEMM2 + fused combine (deterministic 2-way atomics)
    dim3 g2(D_IN / BN, SLOTS / BM);    // (4, 136)
    mma_gemm_kernel<H_DIM, D_IN, false, false>
        <<<g2, 256, SMEM_BYTES>>>(hhi, w2h, b2, out);
}